// round 4
// baseline (speedup 1.0000x reference)
#include <cuda_runtime.h>

#define N_NODES 100000
#define N_EDGES 1600000
#define D_IN    512
#define D_H     128
#define D_OUT   64
#define BN_EPS  1e-5f
#define BN_B    512   // blocks in BN reduction stage 1
#define BN_CHUNK ((N_NODES + BN_B - 1) / BN_B)   // 196

// ---------------- scratch (device globals; no allocation allowed) ------------
__device__ float g_XW0[(size_t)N_NODES * D_H];    // 51.2 MB  x @ W0
__device__ float g_H  [(size_t)N_NODES * D_H];    // 51.2 MB  relu(spmm + b0)
__device__ float g_G  [(size_t)N_NODES * D_OUT];  // 25.6 MB  h_norm @ W1 (+cvec)
__device__ int   g_rowptr[N_NODES + 1];
__device__ float g_part[BN_B * 256];              // per-block (sum[128], sumsq[128])
__device__ float g_W1s[D_H * D_OUT];              // W1 scaled by rsqrt(var+eps)
__device__ float g_cvec[D_OUT];                   // -sum_k mean_k*s_k*W1[k][c]

// ---------------- f32x2 helpers ---------------------------------------------
__device__ __forceinline__ unsigned long long pack2(float x, float y) {
    unsigned long long r;
    asm("mov.b64 %0, {%1, %2};" : "=l"(r) : "f"(x), "f"(y));
    return r;
}
__device__ __forceinline__ float2 unpack2(unsigned long long v) {
    float2 r;
    asm("mov.b64 {%0, %1}, %2;" : "=f"(r.x), "=f"(r.y) : "l"(v));
    return r;
}
#define FFMA2(acc, a2, b2) \
    asm volatile("fma.rn.f32x2 %0, %1, %2, %0;" : "+l"(acc) : "l"(a2), "l"(b2))

// ---------------- CSR offsets from sorted row -------------------------------
__global__ void rowptr_kernel(const int* __restrict__ row) {
    int i = blockIdx.x * blockDim.x + threadIdx.x;
    if (i > N_NODES) return;
    // lower_bound: first index with row[idx] >= i
    int lo = 0, hi = N_EDGES;
    while (lo < hi) {
        int mid = (lo + hi) >> 1;
        if (__ldg(row + mid) < i) lo = mid + 1; else hi = mid;
    }
    g_rowptr[i] = lo;
}

// ---------------- GEMM1: XW0 = x @ W0   (M=100000, N=128, K=512) ------------
// 128x128 block tile, K-tile 16, 256 threads, 8x8 per thread via f32x2 FMA.
__global__ __launch_bounds__(256, 2) void gemm1_kernel(
        const float* __restrict__ X, const float* __restrict__ W0) {
    __shared__ float As[128][17];   // [m][k], padded (conflict-free column reads)
    __shared__ float Bs[16][128];   // [k][n]

    const int tid = threadIdx.x;
    const int mBase = blockIdx.x * 128;
    const int r0 = (tid >> 4) * 8;     // row base within tile
    const int c0 = (tid & 15) * 8;     // col base within tile

    unsigned long long acc[8][4];
#pragma unroll
    for (int i = 0; i < 8; i++)
#pragma unroll
        for (int j = 0; j < 4; j++) acc[i][j] = 0ull;

    for (int kb = 0; kb < D_IN; kb += 16) {
        // load A tile: 128 rows x 16 cols = 512 float4
#pragma unroll
        for (int l = 0; l < 2; l++) {
            int L = tid + l * 256;
            int r = L >> 2, c4 = L & 3;
            int gr = mBase + r;
            if (gr >= N_NODES) gr = N_NODES - 1;
            float4 v = *reinterpret_cast<const float4*>(
                X + (size_t)gr * D_IN + kb + c4 * 4);
            As[r][c4 * 4 + 0] = v.x;
            As[r][c4 * 4 + 1] = v.y;
            As[r][c4 * 4 + 2] = v.z;
            As[r][c4 * 4 + 3] = v.w;
        }
        // load B tile: 16 rows x 128 cols = 512 float4
#pragma unroll
        for (int l = 0; l < 2; l++) {
            int L = tid + l * 256;
            int kk = L >> 5, c4 = L & 31;
            float4 v = *reinterpret_cast<const float4*>(
                W0 + (size_t)(kb + kk) * D_H + c4 * 4);
            *reinterpret_cast<float4*>(&Bs[kk][c4 * 4]) = v;
        }
        __syncthreads();

#pragma unroll
        for (int k = 0; k < 16; k++) {
            float4 b01 = *reinterpret_cast<const float4*>(&Bs[k][c0]);
            float4 b23 = *reinterpret_cast<const float4*>(&Bs[k][c0 + 4]);
            unsigned long long b2[4];
            b2[0] = pack2(b01.x, b01.y);
            b2[1] = pack2(b01.z, b01.w);
            b2[2] = pack2(b23.x, b23.y);
            b2[3] = pack2(b23.z, b23.w);
#pragma unroll
            for (int i = 0; i < 8; i++) {
                float av = As[r0 + i][k];
                unsigned long long a2 = pack2(av, av);
                FFMA2(acc[i][0], a2, b2[0]);
                FFMA2(acc[i][1], a2, b2[1]);
                FFMA2(acc[i][2], a2, b2[2]);
                FFMA2(acc[i][3], a2, b2[3]);
            }
        }
        __syncthreads();
    }

#pragma unroll
    for (int i = 0; i < 8; i++) {
        int gr = mBase + r0 + i;
        if (gr < N_NODES) {
            float2 p0 = unpack2(acc[i][0]);
            float2 p1 = unpack2(acc[i][1]);
            float2 p2 = unpack2(acc[i][2]);
            float2 p3 = unpack2(acc[i][3]);
            float4 o0 = make_float4(p0.x, p0.y, p1.x, p1.y);
            float4 o1 = make_float4(p2.x, p2.y, p3.x, p3.y);
            *reinterpret_cast<float4*>(&g_XW0[(size_t)gr * D_H + c0])     = o0;
            *reinterpret_cast<float4*>(&g_XW0[(size_t)gr * D_H + c0 + 4]) = o1;
        }
    }
}

// ---------------- SpMM1: H = relu(adj @ XW0 + b0)   one warp per node -------
__global__ __launch_bounds__(256) void spmm1_kernel(
        const float* __restrict__ vals, const int* __restrict__ col,
        const float* __restrict__ b0) {
    int w = (blockIdx.x * 256 + threadIdx.x) >> 5;  // node id
    int lane = threadIdx.x & 31;
    if (w >= N_NODES) return;
    int s = g_rowptr[w], e = g_rowptr[w + 1];
    float a0 = 0.f, a1 = 0.f, a2 = 0.f, a3 = 0.f;
    for (int i = s; i < e; i++) {
        float v = __ldg(vals + i);
        int   c = __ldg(col + i);
        const float* p = g_XW0 + (size_t)c * D_H + lane;
        a0 = fmaf(v, __ldg(p),      a0);
        a1 = fmaf(v, __ldg(p + 32), a1);
        a2 = fmaf(v, __ldg(p + 64), a2);
        a3 = fmaf(v, __ldg(p + 96), a3);
    }
    float* d = g_H + (size_t)w * D_H + lane;
    d[0]  = fmaxf(a0 + __ldg(b0 + lane),      0.f);
    d[32] = fmaxf(a1 + __ldg(b0 + lane + 32), 0.f);
    d[64] = fmaxf(a2 + __ldg(b0 + lane + 64), 0.f);
    d[96] = fmaxf(a3 + __ldg(b0 + lane + 96), 0.f);
}

// ---------------- BN reduction stage 1 (deterministic, no atomics) ----------
__global__ __launch_bounds__(256) void bnreduce_kernel() {
    __shared__ float sh[512];
    int tid = threadIdx.x;
    int ch = tid & 127;        // channel
    int sub = tid >> 7;        // 0/1: row parity split
    int r0 = blockIdx.x * BN_CHUNK;
    int r1 = r0 + BN_CHUNK; if (r1 > N_NODES) r1 = N_NODES;
    float s = 0.f, ss = 0.f;
    for (int r = r0 + sub; r < r1; r += 2) {
        float v = g_H[(size_t)r * D_H + ch];
        s += v; ss += v * v;
    }
    sh[tid] = s; sh[256 + tid] = ss;
    __syncthreads();
    if (sub == 0) {
        g_part[blockIdx.x * 256 + ch]       = s  + sh[tid + 128];
        g_part[blockIdx.x * 256 + 128 + ch] = ss + sh[256 + tid + 128];
    }
}

// ---------------- BN finalize + fold into W1 --------------------------------
__global__ __launch_bounds__(256) void finalize_kernel(const float* __restrict__ W1) {
    __shared__ float sm[128], sc[128];
    int tid = threadIdx.x;
    if (tid < 128) {
        float s = 0.f, ss = 0.f;
        for (int b = 0; b < BN_B; b++) {
            s  += g_part[b * 256 + tid];
            ss += g_part[b * 256 + 128 + tid];
        }
        float mean = s / (float)N_NODES;
        float var = ss / (float)N_NODES - mean * mean;
        if (var < 0.f) var = 0.f;
        sm[tid] = mean;
        sc[tid] = rsqrtf(var + BN_EPS);
    }
    __syncthreads();
    for (int i = tid; i < D_H * D_OUT; i += 256) {
        int k = i >> 6;
        g_W1s[i] = __ldg(W1 + i) * sc[k];
    }
    if (tid < 64) {
        float a = 0.f;
        for (int k = 0; k < 128; k++)
            a -= sm[k] * sc[k] * __ldg(W1 + k * 64 + tid);
        g_cvec[tid] = a;
    }
}

// ---------------- GEMM2: G = H @ W1s + cvec   (M=100000, N=64, K=128) -------
// 64 rows x 64 cols per block, 256 threads, 4x4 per thread.
__global__ __launch_bounds__(256) void gemm2_kernel() {
    __shared__ float Hs[128][65];   // [k][m], padded
    __shared__ float Ws[128][64];   // [k][n]
    __shared__ float cv[64];
    int tid = threadIdx.x;
    int nb = blockIdx.x * 64;

#pragma unroll
    for (int l = 0; l < 8; l++) {
        int L = tid + l * 256;
        int k = L >> 4, c4 = L & 15;
        *reinterpret_cast<float4*>(&Ws[k][c4 * 4]) =
            *reinterpret_cast<const float4*>(&g_W1s[k * 64 + c4 * 4]);
    }
#pragma unroll
    for (int l = 0; l < 8; l++) {
        int L = tid + l * 256;
        int r = L >> 5, c4 = L & 31;
        int gr = nb + r; if (gr >= N_NODES) gr = N_NODES - 1;
        float4 v = *reinterpret_cast<const float4*>(&g_H[(size_t)gr * D_H + c4 * 4]);
        Hs[c4 * 4 + 0][r] = v.x;
        Hs[c4 * 4 + 1][r] = v.y;
        Hs[c4 * 4 + 2][r] = v.z;
        Hs[c4 * 4 + 3][r] = v.w;
    }
    if (tid < 64) cv[tid] = g_cvec[tid];
    __syncthreads();

    int r0 = (tid >> 4) * 4, c0 = (tid & 15) * 4;
    unsigned long long acc[4][2];
#pragma unroll
    for (int i = 0; i < 4; i++) { acc[i][0] = 0ull; acc[i][1] = 0ull; }

#pragma unroll 4
    for (int k = 0; k < 128; k++) {
        float4 b = *reinterpret_cast<const float4*>(&Ws[k][c0]);
        unsigned long long b20 = pack2(b.x, b.y);
        unsigned long long b21 = pack2(b.z, b.w);
#pragma unroll
        for (int i = 0; i < 4; i++) {
            float av = Hs[k][r0 + i];
            unsigned long long a2 = pack2(av, av);
            FFMA2(acc[i][0], a2, b20);
            FFMA2(acc[i][1], a2, b21);
        }
    }
#pragma unroll
    for (int i = 0; i < 4; i++) {
        int gr = nb + r0 + i;
        if (gr < N_NODES) {
            float2 p0 = unpack2(acc[i][0]);
            float2 p1 = unpack2(acc[i][1]);
            float4 o = make_float4(p0.x + cv[c0], p0.y + cv[c0 + 1],
                                   p1.x + cv[c0 + 2], p1.y + cv[c0 + 3]);
            *reinterpret_cast<float4*>(&g_G[(size_t)gr * D_OUT + c0]) = o;
        }
    }
}

// ---------------- SpMM2: out = adj @ G + b1 ---------------------------------
__global__ __launch_bounds__(256) void spmm2_kernel(
        const float* __restrict__ vals, const int* __restrict__ col,
        const float* __restrict__ b1, float* __restrict__ out) {
    int w = (blockIdx.x * 256 + threadIdx.x) >> 5;
    int lane = threadIdx.x & 31;
    if (w >= N_NODES) return;
    int s = g_rowptr[w], e = g_rowptr[w + 1];
    float a0 = 0.f, a1 = 0.f;
    for (int i = s; i < e; i++) {
        float v = __ldg(vals + i);
        int   c = __ldg(col + i);
        const float* p = g_G + (size_t)c * D_OUT + lane;
        a0 = fmaf(v, __ldg(p),      a0);
        a1 = fmaf(v, __ldg(p + 32), a1);
    }
    float* d = out + (size_t)w * D_OUT + lane;
    d[0]  = a0 + __ldg(b1 + lane);
    d[32] = a1 + __ldg(b1 + lane + 32);
}

// ---------------- launch ----------------------------------------------------
extern "C" void kernel_launch(void* const* d_in, const int* in_sizes, int n_in,
                              void* d_out, int out_size) {
    const float* x    = (const float*)d_in[0];
    const float* W0   = (const float*)d_in[1];
    const float* b0   = (const float*)d_in[2];
    const float* W1   = (const float*)d_in[3];
    const float* b1   = (const float*)d_in[4];
    const float* adjv = (const float*)d_in[5];
    const int*   row  = (const int*)d_in[6];
    const int*   col  = (const int*)d_in[7];
    float* out = (float*)d_out;

    rowptr_kernel  <<<(N_NODES + 1 + 255) / 256, 256>>>(row);
    gemm1_kernel   <<<(N_NODES + 127) / 128, 256>>>(x, W0);
    spmm1_kernel   <<<(N_NODES + 7) / 8, 256>>>(adjv, col, b0);
    bnreduce_kernel<<<BN_B, 256>>>();
    finalize_kernel<<<1, 256>>>(W1);
    gemm2_kernel   <<<(N_NODES + 63) / 64, 256>>>();
    spmm2_kernel   <<<(N_NODES + 7) / 8, 256>>>(adjv, col, b1, out);
}

// round 8
// speedup vs baseline: 1.5703x; 1.5703x over previous
#include <cuda_runtime.h>
#include <cuda_bf16.h>
#include <cstdint>

#define N_NODES 100000
#define N_EDGES 1600000
#define D_IN    512
#define D_H     128
#define D_OUT   64
#define BN_EPS  1e-5f
#define BN_B    512
#define BN_CHUNK ((N_NODES + BN_B - 1) / BN_B)

// ---------------- scratch (device globals; no allocation allowed) ------------
__device__ float g_XW0[(size_t)N_NODES * D_H];    // 51.2 MB  x @ W0
__device__ float g_H  [(size_t)N_NODES * D_H];    // 51.2 MB  relu(spmm + b0)
__device__ float g_G  [(size_t)N_NODES * D_OUT];  // 25.6 MB
__device__ int   g_rowptr[N_NODES + 1];
__device__ float g_part[BN_B * 256];
__device__ float g_W1s[D_H * D_OUT];
__device__ float g_cvec[D_OUT];
// W0 transposed to [N=128][K=512], split into bf16 hi/lo
__device__ __align__(16) __nv_bfloat16 g_W0T_hi[D_H * D_IN];
__device__ __align__(16) __nv_bfloat16 g_W0T_lo[D_H * D_IN];

// ---------------- f32x2 helpers (gemm2) --------------------------------------
__device__ __forceinline__ unsigned long long pack2(float x, float y) {
    unsigned long long r;
    asm("mov.b64 %0, {%1, %2};" : "=l"(r) : "f"(x), "f"(y));
    return r;
}
__device__ __forceinline__ float2 unpack2(unsigned long long v) {
    float2 r;
    asm("mov.b64 {%0, %1}, %2;" : "=f"(r.x), "=f"(r.y) : "l"(v));
    return r;
}
#define FFMA2(acc, a2, b2) \
    asm volatile("fma.rn.f32x2 %0, %1, %2, %0;" : "+l"(acc) : "l"(a2), "l"(b2))

// ---------------- base-ISA tensor-core helpers (sm_80+, OK on sm_103) --------
__device__ __forceinline__ uint32_t smem_u32(const void* p) {
    uint32_t a;
    asm("{ .reg .u64 t; cvta.to.shared.u64 t, %1; cvt.u32.u64 %0, t; }"
        : "=r"(a) : "l"(p));
    return a;
}
#define LDSM4(r0, r1, r2, r3, addr)                                            \
    asm volatile("ldmatrix.sync.aligned.m8n8.x4.shared.b16 {%0,%1,%2,%3}, [%4];" \
        : "=r"(r0), "=r"(r1), "=r"(r2), "=r"(r3) : "r"(addr))
#define LDSM2(r0, r1, addr)                                                    \
    asm volatile("ldmatrix.sync.aligned.m8n8.x2.shared.b16 {%0,%1}, [%2];"     \
        : "=r"(r0), "=r"(r1) : "r"(addr))
#define MMA16816(d, a, b)                                                      \
    asm volatile("mma.sync.aligned.m16n8k16.row.col.f32.bf16.bf16.f32 "        \
        "{%0,%1,%2,%3}, {%4,%5,%6,%7}, {%8,%9}, {%0,%1,%2,%3};"                \
        : "+f"((d)[0]), "+f"((d)[1]), "+f"((d)[2]), "+f"((d)[3])               \
        : "r"((a)[0]), "r"((a)[1]), "r"((a)[2]), "r"((a)[3]),                  \
          "r"((b)[0]), "r"((b)[1]))

__device__ __forceinline__ uint32_t bfhi_pack(float a, float b,
                                              uint32_t& lo_pack) {
    __nv_bfloat16 ha = __float2bfloat16(a);
    __nv_bfloat16 hb = __float2bfloat16(b);
    float ra = a - __bfloat162float(ha);
    float rb = b - __bfloat162float(hb);
    __nv_bfloat16 la = __float2bfloat16(ra);
    __nv_bfloat16 lb = __float2bfloat16(rb);
    lo_pack = (uint32_t)__bfloat16_as_ushort(la) |
              ((uint32_t)__bfloat16_as_ushort(lb) << 16);
    return (uint32_t)__bfloat16_as_ushort(ha) |
           ((uint32_t)__bfloat16_as_ushort(hb) << 16);
}

// ---------------- CSR offsets from sorted row -------------------------------
__global__ void rowptr_kernel(const int* __restrict__ row) {
    int i = blockIdx.x * blockDim.x + threadIdx.x;
    if (i > N_NODES) return;
    int lo = 0, hi = N_EDGES;
    while (lo < hi) {
        int mid = (lo + hi) >> 1;
        if (__ldg(row + mid) < i) lo = mid + 1; else hi = mid;
    }
    g_rowptr[i] = lo;
}

// ---------------- prep: W0 [512][128] f32 -> W0T hi/lo bf16 [128][512] ------
__global__ void prep_w0_kernel(const float* __restrict__ W0) {
    int i = blockIdx.x * 256 + threadIdx.x;
    if (i >= D_IN * D_H) return;
    int k = i >> 7, n = i & 127;
    float w = __ldg(W0 + i);
    __nv_bfloat16 hb = __float2bfloat16(w);
    float r = w - __bfloat162float(hb);
    g_W0T_hi[n * D_IN + k] = hb;
    g_W0T_lo[n * D_IN + k] = __float2bfloat16(r);
}

// ---------------- GEMM1 via mma.sync bf16 (hi/lo split): XW0 = x @ W0 -------
// CTA tile 128(M) x 128(N), 512 threads = 16 warps (4 m x 4 n), warp tile 32x32.
// K chunks of 64 (4 ksteps of 16). X prefetched one chunk ahead in registers.
#define G1_PAD 72                       // bf16 elems per smem row (144B)
#define G1_MAT (128 * G1_PAD)           // elems per smem matrix
#define G1_SMEM (4 * G1_MAT * 2)        // 73728 bytes

__global__ __launch_bounds__(512, 1) void gemm1_mma_kernel(
        const float* __restrict__ X) {
    extern __shared__ __nv_bfloat16 smb[];
    __nv_bfloat16* AH = smb;
    __nv_bfloat16* AL = smb + G1_MAT;
    __nv_bfloat16* BH = smb + 2 * G1_MAT;
    __nv_bfloat16* BL = smb + 3 * G1_MAT;

    const int tid = threadIdx.x;
    const int wid = tid >> 5;
    const int lid = tid & 31;
    const int mBase = blockIdx.x * 128;
    const int wm = wid & 3;          // warp m index (0..3) -> m offset 32*wm
    const int wn = wid >> 2;         // warp n index (0..3) -> n offset 32*wn

    // --- loader mapping: thread -> (row 0..127, k-quarter 0..3 of 16 elems) --
    const int arow = tid >> 2;
    const int kq   = (tid & 3) * 16;
    int gr = mBase + arow; if (gr >= N_NODES) gr = N_NODES - 1;
    const float4* xsrc = reinterpret_cast<const float4*>(
        X + (size_t)gr * D_IN + kq);

    // --- ldmatrix source addresses (byte, shared) ----------------------------
    const uint32_t ah_base = smem_u32(AH), al_base = smem_u32(AL);
    const uint32_t bh_base = smem_u32(BH), bl_base = smem_u32(BL);
    const int aRow = wm * 32 + (lid & 7) + 8 * ((lid >> 3) & 1);
    const int aKof = 8 * (lid >> 4);
    const int l2   = lid & 15;
    const int bRow = wn * 32 + (l2 & 7);
    const int bKof = 8 * (l2 >> 3);

    float acc[2][4][4];
#pragma unroll
    for (int t = 0; t < 2; t++)
#pragma unroll
        for (int u = 0; u < 4; u++)
#pragma unroll
            for (int q = 0; q < 4; q++) acc[t][u][q] = 0.f;

    float4 xr[4];
#pragma unroll
    for (int j = 0; j < 4; j++) xr[j] = __ldg(xsrc + j);

    for (int c = 0; c < 8; ++c) {
        // --- convert A chunk regs -> smem hi/lo (16B stores, conflict-free) --
        {
            uint32_t h[8], l[8];
#pragma unroll
            for (int j = 0; j < 4; j++) {
                h[2 * j]     = bfhi_pack(xr[j].x, xr[j].y, l[2 * j]);
                h[2 * j + 1] = bfhi_pack(xr[j].z, xr[j].w, l[2 * j + 1]);
            }
            int off = arow * G1_PAD + kq;
            *reinterpret_cast<uint4*>(AH + off)     = make_uint4(h[0], h[1], h[2], h[3]);
            *reinterpret_cast<uint4*>(AH + off + 8) = make_uint4(h[4], h[5], h[6], h[7]);
            *reinterpret_cast<uint4*>(AL + off)     = make_uint4(l[0], l[1], l[2], l[3]);
            *reinterpret_cast<uint4*>(AL + off + 8) = make_uint4(l[4], l[5], l[6], l[7]);
        }
        // --- copy B chunk (prepped bf16 hi/lo) -> smem ----------------------
        {
            size_t gidx = (size_t)arow * D_IN + c * 64 + kq;
            uint4 v0 = __ldg(reinterpret_cast<const uint4*>(g_W0T_hi + gidx));
            uint4 v1 = __ldg(reinterpret_cast<const uint4*>(g_W0T_hi + gidx + 8));
            uint4 w0 = __ldg(reinterpret_cast<const uint4*>(g_W0T_lo + gidx));
            uint4 w1 = __ldg(reinterpret_cast<const uint4*>(g_W0T_lo + gidx + 8));
            int off = arow * G1_PAD + kq;
            *reinterpret_cast<uint4*>(BH + off)     = v0;
            *reinterpret_cast<uint4*>(BH + off + 8) = v1;
            *reinterpret_cast<uint4*>(BL + off)     = w0;
            *reinterpret_cast<uint4*>(BL + off + 8) = w1;
        }
        __syncthreads();

        // --- prefetch next X chunk (overlaps with MMA below) ----------------
        if (c < 7) {
            xsrc += 16;   // advance 64 floats
#pragma unroll
            for (int j = 0; j < 4; j++) xr[j] = __ldg(xsrc + j);
        }

        // --- MMA over 4 ksteps of 16 ----------------------------------------
#pragma unroll
        for (int ks = 0; ks < 4; ++ks) {
            uint32_t ah[2][4], al[2][4], bh[4][2], bl[4][2];
#pragma unroll
            for (int t = 0; t < 2; t++) {
                uint32_t aoff = (uint32_t)(((aRow + t * 16) * G1_PAD) +
                                           ks * 16 + aKof) * 2u;
                LDSM4(ah[t][0], ah[t][1], ah[t][2], ah[t][3], ah_base + aoff);
                LDSM4(al[t][0], al[t][1], al[t][2], al[t][3], al_base + aoff);
            }
#pragma unroll
            for (int u = 0; u < 4; u++) {
                uint32_t boff = (uint32_t)(((bRow + u * 8) * G1_PAD) +
                                           ks * 16 + bKof) * 2u;
                LDSM2(bh[u][0], bh[u][1], bh_base + boff);
                LDSM2(bl[u][0], bl[u][1], bl_base + boff);
            }
#pragma unroll
            for (int t = 0; t < 2; t++)
#pragma unroll
                for (int u = 0; u < 4; u++) {
                    MMA16816(acc[t][u], ah[t], bh[u]);   // hi*hi
                    MMA16816(acc[t][u], ah[t], bl[u]);   // hi*lo
                    MMA16816(acc[t][u], al[t], bh[u]);   // lo*hi
                }
        }
        __syncthreads();
    }

    // --- epilogue: write f32 directly ---------------------------------------
    const int erow = lid >> 2;
    const int ecol = (lid & 3) * 2;
#pragma unroll
    for (int t = 0; t < 2; t++) {
#pragma unroll
        for (int u = 0; u < 4; u++) {
            int r0 = mBase + wm * 32 + t * 16 + erow;
            int cc = wn * 32 + u * 8 + ecol;
            if (r0 < N_NODES)
                *reinterpret_cast<float2*>(g_XW0 + (size_t)r0 * D_H + cc) =
                    make_float2(acc[t][u][0], acc[t][u][1]);
            int r1 = r0 + 8;
            if (r1 < N_NODES)
                *reinterpret_cast<float2*>(g_XW0 + (size_t)r1 * D_H + cc) =
                    make_float2(acc[t][u][2], acc[t][u][3]);
        }
    }
}

// ---------------- SpMM1: H = relu(adj @ XW0 + b0)   one warp per node -------
__global__ __launch_bounds__(256) void spmm1_kernel(
        const float* __restrict__ vals, const int* __restrict__ col,
        const float* __restrict__ b0) {
    int w = (blockIdx.x * 256 + threadIdx.x) >> 5;
    int lane = threadIdx.x & 31;
    if (w >= N_NODES) return;
    int s = g_rowptr[w], e = g_rowptr[w + 1];
    float a0 = 0.f, a1 = 0.f, a2 = 0.f, a3 = 0.f;
    for (int i = s; i < e; i++) {
        float v = __ldg(vals + i);
        int   c = __ldg(col + i);
        const float* p = g_XW0 + (size_t)c * D_H + lane;
        a0 = fmaf(v, __ldg(p),      a0);
        a1 = fmaf(v, __ldg(p + 32), a1);
        a2 = fmaf(v, __ldg(p + 64), a2);
        a3 = fmaf(v, __ldg(p + 96), a3);
    }
    float* d = g_H + (size_t)w * D_H + lane;
    d[0]  = fmaxf(a0 + __ldg(b0 + lane),      0.f);
    d[32] = fmaxf(a1 + __ldg(b0 + lane + 32), 0.f);
    d[64] = fmaxf(a2 + __ldg(b0 + lane + 64), 0.f);
    d[96] = fmaxf(a3 + __ldg(b0 + lane + 96), 0.f);
}

// ---------------- BN reduction stage 1 (deterministic, no atomics) ----------
__global__ __launch_bounds__(256) void bnreduce_kernel() {
    __shared__ float sh[512];
    int tid = threadIdx.x;
    int ch = tid & 127;
    int sub = tid >> 7;
    int r0 = blockIdx.x * BN_CHUNK;
    int r1 = r0 + BN_CHUNK; if (r1 > N_NODES) r1 = N_NODES;
    float s = 0.f, ss = 0.f;
    for (int r = r0 + sub; r < r1; r += 2) {
        float v = g_H[(size_t)r * D_H + ch];
        s += v; ss += v * v;
    }
    sh[tid] = s; sh[256 + tid] = ss;
    __syncthreads();
    if (sub == 0) {
        g_part[blockIdx.x * 256 + ch]       = s  + sh[tid + 128];
        g_part[blockIdx.x * 256 + 128 + ch] = ss + sh[256 + tid + 128];
    }
}

// ---------------- BN finalize + fold into W1 --------------------------------
__global__ __launch_bounds__(256) void finalize_kernel(const float* __restrict__ W1) {
    __shared__ float sm[128], sc[128];
    int tid = threadIdx.x;
    if (tid < 128) {
        float s = 0.f, ss = 0.f;
        for (int b = 0; b < BN_B; b++) {
            s  += g_part[b * 256 + tid];
            ss += g_part[b * 256 + 128 + tid];
        }
        float mean = s / (float)N_NODES;
        float var = ss / (float)N_NODES - mean * mean;
        if (var < 0.f) var = 0.f;
        sm[tid] = mean;
        sc[tid] = rsqrtf(var + BN_EPS);
    }
    __syncthreads();
    for (int i = tid; i < D_H * D_OUT; i += 256) {
        int k = i >> 6;
        g_W1s[i] = __ldg(W1 + i) * sc[k];
    }
    if (tid < 64) {
        float a = 0.f;
        for (int k = 0; k < 128; k++)
            a -= sm[k] * sc[k] * __ldg(W1 + k * 64 + tid);
        g_cvec[tid] = a;
    }
}

// ---------------- GEMM2: G = H @ W1s + cvec   (M=100000, N=64, K=128) -------
__global__ __launch_bounds__(256) void gemm2_kernel() {
    __shared__ float Hs[128][65];
    __shared__ float Ws[128][64];
    __shared__ float cv[64];
    int tid = threadIdx.x;
    int nb = blockIdx.x * 64;

#pragma unroll
    for (int l = 0; l < 8; l++) {
        int L = tid + l * 256;
        int k = L >> 4, c4 = L & 15;
        *reinterpret_cast<float4*>(&Ws[k][c4 * 4]) =
            *reinterpret_cast<const float4*>(&g_W1s[k * 64 + c4 * 4]);
    }
#pragma unroll
    for (int l = 0; l < 8; l++) {
        int L = tid + l * 256;
        int r = L >> 5, c4 = L & 31;
        int gr = nb + r; if (gr >= N_NODES) gr = N_NODES - 1;
        float4 v = *reinterpret_cast<const float4*>(&g_H[(size_t)gr * D_H + c4 * 4]);
        Hs[c4 * 4 + 0][r] = v.x;
        Hs[c4 * 4 + 1][r] = v.y;
        Hs[c4 * 4 + 2][r] = v.z;
        Hs[c4 * 4 + 3][r] = v.w;
    }
    if (tid < 64) cv[tid] = g_cvec[tid];
    __syncthreads();

    int r0 = (tid >> 4) * 4, c0 = (tid & 15) * 4;
    unsigned long long acc[4][2];
#pragma unroll
    for (int i = 0; i < 4; i++) { acc[i][0] = 0ull; acc[i][1] = 0ull; }

#pragma unroll 4
    for (int k = 0; k < 128; k++) {
        float4 b = *reinterpret_cast<const float4*>(&Ws[k][c0]);
        unsigned long long b20 = pack2(b.x, b.y);
        unsigned long long b21 = pack2(b.z, b.w);
#pragma unroll
        for (int i = 0; i < 4; i++) {
            float av = Hs[k][r0 + i];
            unsigned long long a2 = pack2(av, av);
            FFMA2(acc[i][0], a2, b20);
            FFMA2(acc[i][1], a2, b21);
        }
    }
#pragma unroll
    for (int i = 0; i < 4; i++) {
        int gr = nb + r0 + i;
        if (gr < N_NODES) {
            float2 p0 = unpack2(acc[i][0]);
            float2 p1 = unpack2(acc[i][1]);
            float4 o = make_float4(p0.x + cv[c0], p0.y + cv[c0 + 1],
                                   p1.x + cv[c0 + 2], p1.y + cv[c0 + 3]);
            *reinterpret_cast<float4*>(&g_G[(size_t)gr * D_OUT + c0]) = o;
        }
    }
}

// ---------------- SpMM2: out = adj @ G + b1 ---------------------------------
__global__ __launch_bounds__(256) void spmm2_kernel(
        const float* __restrict__ vals, const int* __restrict__ col,
        const float* __restrict__ b1, float* __restrict__ out) {
    int w = (blockIdx.x * 256 + threadIdx.x) >> 5;
    int lane = threadIdx.x & 31;
    if (w >= N_NODES) return;
    int s = g_rowptr[w], e = g_rowptr[w + 1];
    float a0 = 0.f, a1 = 0.f;
    for (int i = s; i < e; i++) {
        float v = __ldg(vals + i);
        int   c = __ldg(col + i);
        const float* p = g_G + (size_t)c * D_OUT + lane;
        a0 = fmaf(v, __ldg(p),      a0);
        a1 = fmaf(v, __ldg(p + 32), a1);
    }
    float* d = out + (size_t)w * D_OUT + lane;
    d[0]  = a0 + __ldg(b1 + lane);
    d[32] = a1 + __ldg(b1 + lane + 32);
}

// ---------------- launch ----------------------------------------------------
extern "C" void kernel_launch(void* const* d_in, const int* in_sizes, int n_in,
                              void* d_out, int out_size) {
    const float* x    = (const float*)d_in[0];
    const float* W0   = (const float*)d_in[1];
    const float* b0   = (const float*)d_in[2];
    const float* W1   = (const float*)d_in[3];
    const float* b1   = (const float*)d_in[4];
    const float* adjv = (const float*)d_in[5];
    const int*   row  = (const int*)d_in[6];
    const int*   col  = (const int*)d_in[7];
    float* out = (float*)d_out;

    cudaFuncSetAttribute(gemm1_mma_kernel,
                         cudaFuncAttributeMaxDynamicSharedMemorySize, G1_SMEM);

    rowptr_kernel   <<<(N_NODES + 1 + 255) / 256, 256>>>(row);
    prep_w0_kernel  <<<(D_IN * D_H + 255) / 256, 256>>>(W0);
    gemm1_mma_kernel<<<(N_NODES + 127) / 128, 512, G1_SMEM>>>(x);
    spmm1_kernel    <<<(N_NODES + 7) / 8, 256>>>(adjv, col, b0);
    bnreduce_kernel <<<BN_B, 256>>>();
    finalize_kernel <<<1, 256>>>(W1);
    gemm2_kernel    <<<(N_NODES + 63) / 64, 256>>>();
    spmm2_kernel    <<<(N_NODES + 7) / 8, 256>>>(adjv, col, b1, out);
}

// round 10
// speedup vs baseline: 1.6538x; 1.0532x over previous
#include <cuda_runtime.h>
#include <cuda_bf16.h>
#include <cstdint>

#define N_NODES 100000
#define N_EDGES 1600000
#define D_IN    512
#define D_H     128
#define D_OUT   64
#define BN_EPS  1e-5f
#define SP1_BLOCKS (N_NODES / 8)        // 12500, exact
#define RED1_BLOCKS 100                 // 12500 = 100 * 125

// ---------------- scratch (device globals; no allocation allowed) ------------
__device__ float g_XW0[(size_t)N_NODES * D_H];            // 51.2 MB
__device__ __align__(16) __nv_bfloat16 g_Hhi[(size_t)N_NODES * D_H];  // 25.6 MB
__device__ __align__(16) __nv_bfloat16 g_Hlo[(size_t)N_NODES * D_H];  // 25.6 MB
__device__ float g_G  [(size_t)N_NODES * D_OUT];          // 25.6 MB
__device__ int   g_rowptr[N_NODES + 1];
__device__ float g_part [SP1_BLOCKS * 256];               // 12.8 MB
__device__ float g_part2[RED1_BLOCKS * 256];
__device__ float g_cvec[D_OUT];
__device__ __align__(16) __nv_bfloat16 g_W0T_hi[D_H * D_IN];
__device__ __align__(16) __nv_bfloat16 g_W0T_lo[D_H * D_IN];
__device__ __align__(16) __nv_bfloat16 g_W1T_hi[D_OUT * D_H];  // [n][k] scaled
__device__ __align__(16) __nv_bfloat16 g_W1T_lo[D_OUT * D_H];

// ---------------- base-ISA tensor-core helpers (sm_80+, OK on sm_103) --------
__device__ __forceinline__ uint32_t smem_u32(const void* p) {
    uint32_t a;
    asm("{ .reg .u64 t; cvta.to.shared.u64 t, %1; cvt.u32.u64 %0, t; }"
        : "=r"(a) : "l"(p));
    return a;
}
#define LDSM4(r0, r1, r2, r3, addr)                                            \
    asm volatile("ldmatrix.sync.aligned.m8n8.x4.shared.b16 {%0,%1,%2,%3}, [%4];" \
        : "=r"(r0), "=r"(r1), "=r"(r2), "=r"(r3) : "r"(addr))
#define LDSM2(r0, r1, addr)                                                    \
    asm volatile("ldmatrix.sync.aligned.m8n8.x2.shared.b16 {%0,%1}, [%2];"     \
        : "=r"(r0), "=r"(r1) : "r"(addr))
#define MMA16816(d, a, b)                                                      \
    asm volatile("mma.sync.aligned.m16n8k16.row.col.f32.bf16.bf16.f32 "        \
        "{%0,%1,%2,%3}, {%4,%5,%6,%7}, {%8,%9}, {%0,%1,%2,%3};"                \
        : "+f"((d)[0]), "+f"((d)[1]), "+f"((d)[2]), "+f"((d)[3])               \
        : "r"((a)[0]), "r"((a)[1]), "r"((a)[2]), "r"((a)[3]),                  \
          "r"((b)[0]), "r"((b)[1]))

__device__ __forceinline__ uint32_t bfhi_pack(float a, float b,
                                              uint32_t& lo_pack) {
    __nv_bfloat16 ha = __float2bfloat16(a);
    __nv_bfloat16 hb = __float2bfloat16(b);
    float ra = a - __bfloat162float(ha);
    float rb = b - __bfloat162float(hb);
    __nv_bfloat16 la = __float2bfloat16(ra);
    __nv_bfloat16 lb = __float2bfloat16(rb);
    lo_pack = (uint32_t)__bfloat16_as_ushort(la) |
              ((uint32_t)__bfloat16_as_ushort(lb) << 16);
    return (uint32_t)__bfloat16_as_ushort(ha) |
           ((uint32_t)__bfloat16_as_ushort(hb) << 16);
}

// ---------------- CSR offsets from sorted row -------------------------------
__global__ void rowptr_kernel(const int* __restrict__ row) {
    int i = blockIdx.x * blockDim.x + threadIdx.x;
    if (i > N_NODES) return;
    int lo = 0, hi = N_EDGES;
    while (lo < hi) {
        int mid = (lo + hi) >> 1;
        if (__ldg(row + mid) < i) lo = mid + 1; else hi = mid;
    }
    g_rowptr[i] = lo;
}

// ---------------- prep: W0 [512][128] f32 -> W0T hi/lo bf16 [128][512] ------
__global__ void prep_w0_kernel(const float* __restrict__ W0) {
    int i = blockIdx.x * 256 + threadIdx.x;
    if (i >= D_IN * D_H) return;
    int k = i >> 7, n = i & 127;
    float w = __ldg(W0 + i);
    __nv_bfloat16 hb = __float2bfloat16(w);
    float r = w - __bfloat162float(hb);
    g_W0T_hi[n * D_IN + k] = hb;
    g_W0T_lo[n * D_IN + k] = __float2bfloat16(r);
}

// ---------------- GEMM1 via mma.sync bf16 (hi/lo split): XW0 = x @ W0 -------
#define G1_PAD 72
#define G1_MAT (128 * G1_PAD)
#define G1_SMEM (4 * G1_MAT * 2)        // 73728 bytes

__global__ __launch_bounds__(512, 1) void gemm1_mma_kernel(
        const float* __restrict__ X) {
    extern __shared__ __nv_bfloat16 smb[];
    __nv_bfloat16* AH = smb;
    __nv_bfloat16* AL = smb + G1_MAT;
    __nv_bfloat16* BH = smb + 2 * G1_MAT;
    __nv_bfloat16* BL = smb + 3 * G1_MAT;

    const int tid = threadIdx.x;
    const int wid = tid >> 5;
    const int lid = tid & 31;
    const int mBase = blockIdx.x * 128;
    const int wm = wid & 3;
    const int wn = wid >> 2;

    const int arow = tid >> 2;
    const int kq   = (tid & 3) * 16;
    int gr = mBase + arow; if (gr >= N_NODES) gr = N_NODES - 1;
    const float4* xsrc = reinterpret_cast<const float4*>(
        X + (size_t)gr * D_IN + kq);

    const uint32_t ah_base = smem_u32(AH), al_base = smem_u32(AL);
    const uint32_t bh_base = smem_u32(BH), bl_base = smem_u32(BL);
    const int aRow = wm * 32 + (lid & 7) + 8 * ((lid >> 3) & 1);
    const int aKof = 8 * (lid >> 4);
    const int l2   = lid & 15;
    const int bRow = wn * 32 + (l2 & 7);
    const int bKof = 8 * (l2 >> 3);

    float acc[2][4][4];
#pragma unroll
    for (int t = 0; t < 2; t++)
#pragma unroll
        for (int u = 0; u < 4; u++)
#pragma unroll
            for (int q = 0; q < 4; q++) acc[t][u][q] = 0.f;

    float4 xr[4];
#pragma unroll
    for (int j = 0; j < 4; j++) xr[j] = __ldg(xsrc + j);

    for (int c = 0; c < 8; ++c) {
        {
            uint32_t h[8], l[8];
#pragma unroll
            for (int j = 0; j < 4; j++) {
                h[2 * j]     = bfhi_pack(xr[j].x, xr[j].y, l[2 * j]);
                h[2 * j + 1] = bfhi_pack(xr[j].z, xr[j].w, l[2 * j + 1]);
            }
            int off = arow * G1_PAD + kq;
            *reinterpret_cast<uint4*>(AH + off)     = make_uint4(h[0], h[1], h[2], h[3]);
            *reinterpret_cast<uint4*>(AH + off + 8) = make_uint4(h[4], h[5], h[6], h[7]);
            *reinterpret_cast<uint4*>(AL + off)     = make_uint4(l[0], l[1], l[2], l[3]);
            *reinterpret_cast<uint4*>(AL + off + 8) = make_uint4(l[4], l[5], l[6], l[7]);
        }
        {
            size_t gidx = (size_t)arow * D_IN + c * 64 + kq;
            uint4 v0 = __ldg(reinterpret_cast<const uint4*>(g_W0T_hi + gidx));
            uint4 v1 = __ldg(reinterpret_cast<const uint4*>(g_W0T_hi + gidx + 8));
            uint4 w0 = __ldg(reinterpret_cast<const uint4*>(g_W0T_lo + gidx));
            uint4 w1 = __ldg(reinterpret_cast<const uint4*>(g_W0T_lo + gidx + 8));
            int off = arow * G1_PAD + kq;
            *reinterpret_cast<uint4*>(BH + off)     = v0;
            *reinterpret_cast<uint4*>(BH + off + 8) = v1;
            *reinterpret_cast<uint4*>(BL + off)     = w0;
            *reinterpret_cast<uint4*>(BL + off + 8) = w1;
        }
        __syncthreads();

        if (c < 7) {
            xsrc += 16;
#pragma unroll
            for (int j = 0; j < 4; j++) xr[j] = __ldg(xsrc + j);
        }

#pragma unroll
        for (int ks = 0; ks < 4; ++ks) {
            uint32_t ah[2][4], al[2][4], bh[4][2], bl[4][2];
#pragma unroll
            for (int t = 0; t < 2; t++) {
                uint32_t aoff = (uint32_t)(((aRow + t * 16) * G1_PAD) +
                                           ks * 16 + aKof) * 2u;
                LDSM4(ah[t][0], ah[t][1], ah[t][2], ah[t][3], ah_base + aoff);
                LDSM4(al[t][0], al[t][1], al[t][2], al[t][3], al_base + aoff);
            }
#pragma unroll
            for (int u = 0; u < 4; u++) {
                uint32_t boff = (uint32_t)(((bRow + u * 8) * G1_PAD) +
                                           ks * 16 + bKof) * 2u;
                LDSM2(bh[u][0], bh[u][1], bh_base + boff);
                LDSM2(bl[u][0], bl[u][1], bl_base + boff);
            }
#pragma unroll
            for (int t = 0; t < 2; t++)
#pragma unroll
                for (int u = 0; u < 4; u++) {
                    MMA16816(acc[t][u], ah[t], bh[u]);
                    MMA16816(acc[t][u], ah[t], bl[u]);
                    MMA16816(acc[t][u], al[t], bh[u]);
                }
        }
        __syncthreads();
    }

    const int erow = lid >> 2;
    const int ecol = (lid & 3) * 2;
#pragma unroll
    for (int t = 0; t < 2; t++) {
#pragma unroll
        for (int u = 0; u < 4; u++) {
            int r0 = mBase + wm * 32 + t * 16 + erow;
            int cc = wn * 32 + u * 8 + ecol;
            if (r0 < N_NODES)
                *reinterpret_cast<float2*>(g_XW0 + (size_t)r0 * D_H + cc) =
                    make_float2(acc[t][u][0], acc[t][u][1]);
            int r1 = r0 + 8;
            if (r1 < N_NODES)
                *reinterpret_cast<float2*>(g_XW0 + (size_t)r1 * D_H + cc) =
                    make_float2(acc[t][u][2], acc[t][u][3]);
        }
    }
}

// ---------------- SpMM1 fused: H(bf16 hi/lo) = relu(adj@XW0 + b0), BN partials
// 8 nodes per block (grid = 12500 exactly, no early-outs). One warp per node.
__global__ __launch_bounds__(256) void spmm1_kernel(
        const float* __restrict__ vals, const int* __restrict__ col,
        const float* __restrict__ b0) {
    __shared__ float sh[1024];
    const int tid  = threadIdx.x;
    const int wid  = tid >> 5;
    const int lane = tid & 31;
    const int w = blockIdx.x * 8 + wid;

    const int s = g_rowptr[w], e = g_rowptr[w + 1];
    float a0 = 0.f, a1 = 0.f, a2 = 0.f, a3 = 0.f;
    int i = s;
    for (; i + 2 <= e; i += 2) {
        float v0 = __ldg(vals + i);
        float v1 = __ldg(vals + i + 1);
        int   c0 = __ldg(col + i);
        int   c1 = __ldg(col + i + 1);
        const float* p0 = g_XW0 + (size_t)c0 * D_H + lane;
        const float* p1 = g_XW0 + (size_t)c1 * D_H + lane;
        float x0 = __ldg(p0), x1 = __ldg(p0 + 32), x2 = __ldg(p0 + 64), x3 = __ldg(p0 + 96);
        float y0 = __ldg(p1), y1 = __ldg(p1 + 32), y2 = __ldg(p1 + 64), y3 = __ldg(p1 + 96);
        a0 = fmaf(v0, x0, a0); a1 = fmaf(v0, x1, a1);
        a2 = fmaf(v0, x2, a2); a3 = fmaf(v0, x3, a3);
        a0 = fmaf(v1, y0, a0); a1 = fmaf(v1, y1, a1);
        a2 = fmaf(v1, y2, a2); a3 = fmaf(v1, y3, a3);
    }
    if (i < e) {
        float v = __ldg(vals + i);
        int   c = __ldg(col + i);
        const float* p = g_XW0 + (size_t)c * D_H + lane;
        a0 = fmaf(v, __ldg(p),      a0);
        a1 = fmaf(v, __ldg(p + 32), a1);
        a2 = fmaf(v, __ldg(p + 64), a2);
        a3 = fmaf(v, __ldg(p + 96), a3);
    }
    float h0 = fmaxf(a0 + __ldg(b0 + lane),      0.f);
    float h1 = fmaxf(a1 + __ldg(b0 + lane + 32), 0.f);
    float h2 = fmaxf(a2 + __ldg(b0 + lane + 64), 0.f);
    float h3 = fmaxf(a3 + __ldg(b0 + lane + 96), 0.f);

    // write bf16 hi/lo H
    const size_t base = (size_t)w * D_H + lane;
    __nv_bfloat16 bh0 = __float2bfloat16(h0);
    __nv_bfloat16 bh1 = __float2bfloat16(h1);
    __nv_bfloat16 bh2 = __float2bfloat16(h2);
    __nv_bfloat16 bh3 = __float2bfloat16(h3);
    g_Hhi[base]      = bh0;
    g_Hhi[base + 32] = bh1;
    g_Hhi[base + 64] = bh2;
    g_Hhi[base + 96] = bh3;
    g_Hlo[base]      = __float2bfloat16(h0 - __bfloat162float(bh0));
    g_Hlo[base + 32] = __float2bfloat16(h1 - __bfloat162float(bh1));
    g_Hlo[base + 64] = __float2bfloat16(h2 - __bfloat162float(bh2));
    g_Hlo[base + 96] = __float2bfloat16(h3 - __bfloat162float(bh3));

    // BN partials: block-level (sum, sumsq) per channel, deterministic order
    sh[wid * 128 + lane]      = h0;
    sh[wid * 128 + lane + 32] = h1;
    sh[wid * 128 + lane + 64] = h2;
    sh[wid * 128 + lane + 96] = h3;
    __syncthreads();
    if (tid < 128) {
        float s_ = 0.f, ss_ = 0.f;
#pragma unroll
        for (int j = 0; j < 8; j++) {
            float v = sh[j * 128 + tid];
            s_ += v; ss_ += v * v;
        }
        g_part[blockIdx.x * 256 + tid]       = s_;
        g_part[blockIdx.x * 256 + 128 + tid] = ss_;
    }
}

// ---------------- BN reduce stage 2: 12500 partials -> 100 -----------------
__global__ __launch_bounds__(256) void reduce1_kernel() {
    __shared__ float sh[512];
    int tid = threadIdx.x;
    int ch = tid & 127, half = tid >> 7;
    int b0 = blockIdx.x * 125;
    float s = 0.f, ss = 0.f;
    for (int b = b0 + half; b < b0 + 125; b += 2) {
        s  += g_part[b * 256 + ch];
        ss += g_part[b * 256 + 128 + ch];
    }
    sh[tid] = s; sh[256 + tid] = ss;
    __syncthreads();
    if (half == 0) {
        g_part2[blockIdx.x * 256 + ch]       = s  + sh[tid + 128];
        g_part2[blockIdx.x * 256 + 128 + ch] = ss + sh[256 + tid + 128];
    }
}

// ---------------- BN finalize + fold scale into W1 (bf16 hi/lo, transposed) -
__global__ __launch_bounds__(256) void finalize_kernel(const float* __restrict__ W1) {
    __shared__ float sm[128], sc[128];
    int tid = threadIdx.x;
    if (tid < 128) {
        float s = 0.f, ss = 0.f;
        for (int b = 0; b < RED1_BLOCKS; b++) {
            s  += g_part2[b * 256 + tid];
            ss += g_part2[b * 256 + 128 + tid];
        }
        float mean = s / (float)N_NODES;
        float var = ss / (float)N_NODES - mean * mean;
        if (var < 0.f) var = 0.f;
        sm[tid] = mean;
        sc[tid] = rsqrtf(var + BN_EPS);
    }
    __syncthreads();
    for (int i = tid; i < D_H * D_OUT; i += 256) {
        int k = i >> 6, n = i & 63;
        float w = __ldg(W1 + i) * sc[k];
        __nv_bfloat16 hb = __float2bfloat16(w);
        g_W1T_hi[n * D_H + k] = hb;
        g_W1T_lo[n * D_H + k] = __float2bfloat16(w - __bfloat162float(hb));
    }
    if (tid < 64) {
        float a = 0.f;
        for (int k = 0; k < 128; k++)
            a -= sm[k] * sc[k] * __ldg(W1 + k * 64 + tid);
        g_cvec[tid] = a;
    }
}

// ---------------- GEMM2 via mma.sync: G = H @ W1s + cvec --------------------
// CTA 128(M) x 64(N), 256 threads = 8 warps (4m x 2n), warp tile 32x32.
// A = Hhi/Hlo (pre-split by spmm1), B = W1T hi/lo (pre-split by finalize).
#define G2_PAD 72
#define G2_A_MAT (128 * G2_PAD)
#define G2_B_MAT (64 * G2_PAD)
#define G2_SMEM ((2 * G2_A_MAT + 2 * G2_B_MAT) * 2)   // 55296 bytes

__global__ __launch_bounds__(256, 2) void gemm2_mma_kernel() {
    extern __shared__ __nv_bfloat16 smb2[];
    __nv_bfloat16* AH = smb2;
    __nv_bfloat16* AL = AH + G2_A_MAT;
    __nv_bfloat16* BH = AL + G2_A_MAT;
    __nv_bfloat16* BL = BH + G2_B_MAT;

    const int tid = threadIdx.x;
    const int wid = tid >> 5;
    const int lid = tid & 31;
    const int mBase = blockIdx.x * 128;
    const int wm = wid & 3;
    const int wn = wid >> 2;

    const uint32_t ah_base = smem_u32(AH), al_base = smem_u32(AL);
    const uint32_t bh_base = smem_u32(BH), bl_base = smem_u32(BL);
    const int aRow = wm * 32 + (lid & 7) + 8 * ((lid >> 3) & 1);
    const int aKof = 8 * (lid >> 4);
    const int l2   = lid & 15;
    const int bRow = wn * 32 + (l2 & 7);
    const int bKof = 8 * (l2 >> 3);

    float acc[2][4][4];
#pragma unroll
    for (int t = 0; t < 2; t++)
#pragma unroll
        for (int u = 0; u < 4; u++)
#pragma unroll
            for (int q = 0; q < 4; q++) acc[t][u][q] = 0.f;

    for (int c = 0; c < 2; ++c) {
        // A copy: 128 rows x 64 bf16 (hi+lo)
#pragma unroll
        for (int i = 0; i < 4; ++i) {
            int u = tid + i * 256;
            int r = u >> 3, u8 = u & 7;
            int gr = mBase + r; if (gr >= N_NODES) gr = N_NODES - 1;
            size_t gidx = (size_t)gr * D_H + c * 64 + u8 * 8;
            uint4 vh = __ldg(reinterpret_cast<const uint4*>(g_Hhi + gidx));
            uint4 vl = __ldg(reinterpret_cast<const uint4*>(g_Hlo + gidx));
            *reinterpret_cast<uint4*>(AH + r * G2_PAD + u8 * 8) = vh;
            *reinterpret_cast<uint4*>(AL + r * G2_PAD + u8 * 8) = vl;
        }
        // B copy: 64 rows x 64 bf16 (hi+lo)
#pragma unroll
        for (int i = 0; i < 2; ++i) {
            int u = tid + i * 256;
            int r = u >> 3, u8 = u & 7;
            size_t gidx = (size_t)r * D_H + c * 64 + u8 * 8;
            uint4 vh = __ldg(reinterpret_cast<const uint4*>(g_W1T_hi + gidx));
            uint4 vl = __ldg(reinterpret_cast<const uint4*>(g_W1T_lo + gidx));
            *reinterpret_cast<uint4*>(BH + r * G2_PAD + u8 * 8) = vh;
            *reinterpret_cast<uint4*>(BL + r * G2_PAD + u8 * 8) = vl;
        }
        __syncthreads();

#pragma unroll
        for (int ks = 0; ks < 4; ++ks) {
            uint32_t ah[2][4], al[2][4], bh[4][2], bl[4][2];
#pragma unroll
            for (int t = 0; t < 2; t++) {
                uint32_t aoff = (uint32_t)(((aRow + t * 16) * G2_PAD) +
                                           ks * 16 + aKof) * 2u;
                LDSM4(ah[t][0], ah[t][1], ah[t][2], ah[t][3], ah_base + aoff);
                LDSM4(al[t][0], al[t][1], al[t][2], al[t][3], al_base + aoff);
            }
#pragma unroll
            for (int u = 0; u < 4; u++) {
                uint32_t boff = (uint32_t)(((bRow + u * 8) * G2_PAD) +
                                           ks * 16 + bKof) * 2u;
                LDSM2(bh[u][0], bh[u][1], bh_base + boff);
                LDSM2(bl[u][0], bl[u][1], bl_base + boff);
            }
#pragma unroll
            for (int t = 0; t < 2; t++)
#pragma unroll
                for (int u = 0; u < 4; u++) {
                    MMA16816(acc[t][u], ah[t], bh[u]);
                    MMA16816(acc[t][u], ah[t], bl[u]);
                    MMA16816(acc[t][u], al[t], bh[u]);
                }
        }
        __syncthreads();
    }

    const int erow = lid >> 2;
    const int ecol = (lid & 3) * 2;
#pragma unroll
    for (int t = 0; t < 2; t++) {
#pragma unroll
        for (int u = 0; u < 4; u++) {
            int cc = wn * 32 + u * 8 + ecol;
            float cv0 = g_cvec[cc], cv1 = g_cvec[cc + 1];
            int r0 = mBase + wm * 32 + t * 16 + erow;
            if (r0 < N_NODES)
                *reinterpret_cast<float2*>(g_G + (size_t)r0 * D_OUT + cc) =
                    make_float2(acc[t][u][0] + cv0, acc[t][u][1] + cv1);
            int r1 = r0 + 8;
            if (r1 < N_NODES)
                *reinterpret_cast<float2*>(g_G + (size_t)r1 * D_OUT + cc) =
                    make_float2(acc[t][u][2] + cv0, acc[t][u][3] + cv1);
        }
    }
}

// ---------------- SpMM2: out = adj @ G + b1 (unrolled x2) -------------------
__global__ __launch_bounds__(256) void spmm2_kernel(
        const float* __restrict__ vals, const int* __restrict__ col,
        const float* __restrict__ b1, float* __restrict__ out) {
    int w = (blockIdx.x * 256 + threadIdx.x) >> 5;
    int lane = threadIdx.x & 31;
    if (w >= N_NODES) return;
    int s = g_rowptr[w], e = g_rowptr[w + 1];
    float a0 = 0.f, a1 = 0.f;
    int i = s;
    for (; i + 2 <= e; i += 2) {
        float v0 = __ldg(vals + i);
        float v1 = __ldg(vals + i + 1);
        int   c0 = __ldg(col + i);
        int   c1 = __ldg(col + i + 1);
        const float* p0 = g_G + (size_t)c0 * D_OUT + lane;
        const float* p1 = g_G + (size_t)c1 * D_OUT + lane;
        float x0 = __ldg(p0), x1 = __ldg(p0 + 32);
        float y0 = __ldg(p1), y1 = __ldg(p1 + 32);
        a0 = fmaf(v0, x0, a0); a1 = fmaf(v0, x1, a1);
        a0 = fmaf(v1, y0, a0); a1 = fmaf(v1, y1, a1);
    }
    if (i < e) {
        float v = __ldg(vals + i);
        int   c = __ldg(col + i);
        const float* p = g_G + (size_t)c * D_OUT + lane;
        a0 = fmaf(v, __ldg(p),      a0);
        a1 = fmaf(v, __ldg(p + 32), a1);
    }
    float* d = out + (size_t)w * D_OUT + lane;
    d[0]  = a0 + __ldg(b1 + lane);
    d[32] = a1 + __ldg(b1 + lane + 32);
}

// ---------------- launch ----------------------------------------------------
extern "C" void kernel_launch(void* const* d_in, const int* in_sizes, int n_in,
                              void* d_out, int out_size) {
    const float* x    = (const float*)d_in[0];
    const float* W0   = (const float*)d_in[1];
    const float* b0   = (const float*)d_in[2];
    const float* W1   = (const float*)d_in[3];
    const float* b1   = (const float*)d_in[4];
    const float* adjv = (const float*)d_in[5];
    const int*   row  = (const int*)d_in[6];
    const int*   col  = (const int*)d_in[7];
    float* out = (float*)d_out;

    cudaFuncSetAttribute(gemm1_mma_kernel,
                         cudaFuncAttributeMaxDynamicSharedMemorySize, G1_SMEM);
    cudaFuncSetAttribute(gemm2_mma_kernel,
                         cudaFuncAttributeMaxDynamicSharedMemorySize, G2_SMEM);

    rowptr_kernel   <<<(N_NODES + 1 + 255) / 256, 256>>>(row);
    prep_w0_kernel  <<<(D_IN * D_H + 255) / 256, 256>>>(W0);
    gemm1_mma_kernel<<<(N_NODES + 127) / 128, 512, G1_SMEM>>>(x);
    spmm1_kernel    <<<SP1_BLOCKS, 256>>>(adjv, col, b0);
    reduce1_kernel  <<<RED1_BLOCKS, 256>>>();
    finalize_kernel <<<1, 256>>>(W1);
    gemm2_mma_kernel<<<(N_NODES + 127) / 128, 256, G2_SMEM>>>();
    spmm2_kernel    <<<(N_NODES + 7) / 8, 256>>>(adjv, col, b1, out);
}

// round 11
// speedup vs baseline: 1.7769x; 1.0744x over previous
#include <cuda_runtime.h>
#include <cuda_bf16.h>
#include <cuda_fp16.h>
#include <cstdint>

#define N_NODES 100000
#define N_EDGES 1600000
#define D_IN    512
#define D_H     128
#define D_OUT   64
#define BN_EPS  1e-5f
#define SP1_BLOCKS (N_NODES / 8)        // 12500, exact
#define RED1_BLOCKS 100                 // 12500 = 100 * 125

// ---------------- scratch (device globals; no allocation allowed) ------------
__device__ __align__(16) __half g_XW0h[(size_t)N_NODES * D_H];        // 25.6 MB
__device__ __align__(16) __nv_bfloat16 g_Hhi[(size_t)N_NODES * D_H];  // 25.6 MB
__device__ __align__(16) __nv_bfloat16 g_Hlo[(size_t)N_NODES * D_H];  // 25.6 MB
__device__ __align__(16) __half g_Gh[(size_t)N_NODES * D_OUT];        // 12.8 MB
__device__ int   g_rowptr[N_NODES + 1];
__device__ float g_part [SP1_BLOCKS * 256];               // 12.8 MB
__device__ float g_part2[RED1_BLOCKS * 256];
__device__ float g_cvec[D_OUT];
__device__ __align__(16) __nv_bfloat16 g_W0T_hi[D_H * D_IN];
__device__ __align__(16) __nv_bfloat16 g_W0T_lo[D_H * D_IN];
__device__ __align__(16) __nv_bfloat16 g_W1T_hi[D_OUT * D_H];  // [n][k] scaled
__device__ __align__(16) __nv_bfloat16 g_W1T_lo[D_OUT * D_H];

// ---------------- base-ISA tensor-core helpers (sm_80+, OK on sm_103) --------
__device__ __forceinline__ uint32_t smem_u32(const void* p) {
    uint32_t a;
    asm("{ .reg .u64 t; cvta.to.shared.u64 t, %1; cvt.u32.u64 %0, t; }"
        : "=r"(a) : "l"(p));
    return a;
}
#define LDSM4(r0, r1, r2, r3, addr)                                            \
    asm volatile("ldmatrix.sync.aligned.m8n8.x4.shared.b16 {%0,%1,%2,%3}, [%4];" \
        : "=r"(r0), "=r"(r1), "=r"(r2), "=r"(r3) : "r"(addr))
#define LDSM2(r0, r1, addr)                                                    \
    asm volatile("ldmatrix.sync.aligned.m8n8.x2.shared.b16 {%0,%1}, [%2];"     \
        : "=r"(r0), "=r"(r1) : "r"(addr))
#define MMA16816(d, a, b)                                                      \
    asm volatile("mma.sync.aligned.m16n8k16.row.col.f32.bf16.bf16.f32 "        \
        "{%0,%1,%2,%3}, {%4,%5,%6,%7}, {%8,%9}, {%0,%1,%2,%3};"                \
        : "+f"((d)[0]), "+f"((d)[1]), "+f"((d)[2]), "+f"((d)[3])               \
        : "r"((a)[0]), "r"((a)[1]), "r"((a)[2]), "r"((a)[3]),                  \
          "r"((b)[0]), "r"((b)[1]))

__device__ __forceinline__ uint32_t bfhi_pack(float a, float b,
                                              uint32_t& lo_pack) {
    __nv_bfloat16 ha = __float2bfloat16(a);
    __nv_bfloat16 hb = __float2bfloat16(b);
    float ra = a - __bfloat162float(ha);
    float rb = b - __bfloat162float(hb);
    __nv_bfloat16 la = __float2bfloat16(ra);
    __nv_bfloat16 lb = __float2bfloat16(rb);
    lo_pack = (uint32_t)__bfloat16_as_ushort(la) |
              ((uint32_t)__bfloat16_as_ushort(lb) << 16);
    return (uint32_t)__bfloat16_as_ushort(ha) |
           ((uint32_t)__bfloat16_as_ushort(hb) << 16);
}

// ---------------- CSR offsets from sorted row -------------------------------
__global__ void rowptr_kernel(const int* __restrict__ row) {
    int i = blockIdx.x * blockDim.x + threadIdx.x;
    if (i > N_NODES) return;
    int lo = 0, hi = N_EDGES;
    while (lo < hi) {
        int mid = (lo + hi) >> 1;
        if (__ldg(row + mid) < i) lo = mid + 1; else hi = mid;
    }
    g_rowptr[i] = lo;
}

// ---------------- prep: W0 [512][128] f32 -> W0T hi/lo bf16 [128][512] ------
__global__ void prep_w0_kernel(const float* __restrict__ W0) {
    int i = blockIdx.x * 256 + threadIdx.x;
    if (i >= D_IN * D_H) return;
    int k = i >> 7, n = i & 127;
    float w = __ldg(W0 + i);
    __nv_bfloat16 hb = __float2bfloat16(w);
    float r = w - __bfloat162float(hb);
    g_W0T_hi[n * D_IN + k] = hb;
    g_W0T_lo[n * D_IN + k] = __float2bfloat16(r);
}

// ---------------- GEMM1 via mma.sync bf16 (hi/lo split): XW0 = x @ W0 -------
// Epilogue writes fp16 (feeds the L2-bandwidth-bound gather in spmm1).
#define G1_PAD 72
#define G1_MAT (128 * G1_PAD)
#define G1_SMEM (4 * G1_MAT * 2)        // 73728 bytes

__global__ __launch_bounds__(512, 1) void gemm1_mma_kernel(
        const float* __restrict__ X) {
    extern __shared__ __nv_bfloat16 smb[];
    __nv_bfloat16* AH = smb;
    __nv_bfloat16* AL = smb + G1_MAT;
    __nv_bfloat16* BH = smb + 2 * G1_MAT;
    __nv_bfloat16* BL = smb + 3 * G1_MAT;

    const int tid = threadIdx.x;
    const int wid = tid >> 5;
    const int lid = tid & 31;
    const int mBase = blockIdx.x * 128;
    const int wm = wid & 3;
    const int wn = wid >> 2;

    const int arow = tid >> 2;
    const int kq   = (tid & 3) * 16;
    int gr = mBase + arow; if (gr >= N_NODES) gr = N_NODES - 1;
    const float4* xsrc = reinterpret_cast<const float4*>(
        X + (size_t)gr * D_IN + kq);

    const uint32_t ah_base = smem_u32(AH), al_base = smem_u32(AL);
    const uint32_t bh_base = smem_u32(BH), bl_base = smem_u32(BL);
    const int aRow = wm * 32 + (lid & 7) + 8 * ((lid >> 3) & 1);
    const int aKof = 8 * (lid >> 4);
    const int l2   = lid & 15;
    const int bRow = wn * 32 + (l2 & 7);
    const int bKof = 8 * (l2 >> 3);

    float acc[2][4][4];
#pragma unroll
    for (int t = 0; t < 2; t++)
#pragma unroll
        for (int u = 0; u < 4; u++)
#pragma unroll
            for (int q = 0; q < 4; q++) acc[t][u][q] = 0.f;

    float4 xr[4];
#pragma unroll
    for (int j = 0; j < 4; j++) xr[j] = __ldg(xsrc + j);

    for (int c = 0; c < 8; ++c) {
        {
            uint32_t h[8], l[8];
#pragma unroll
            for (int j = 0; j < 4; j++) {
                h[2 * j]     = bfhi_pack(xr[j].x, xr[j].y, l[2 * j]);
                h[2 * j + 1] = bfhi_pack(xr[j].z, xr[j].w, l[2 * j + 1]);
            }
            int off = arow * G1_PAD + kq;
            *reinterpret_cast<uint4*>(AH + off)     = make_uint4(h[0], h[1], h[2], h[3]);
            *reinterpret_cast<uint4*>(AH + off + 8) = make_uint4(h[4], h[5], h[6], h[7]);
            *reinterpret_cast<uint4*>(AL + off)     = make_uint4(l[0], l[1], l[2], l[3]);
            *reinterpret_cast<uint4*>(AL + off + 8) = make_uint4(l[4], l[5], l[6], l[7]);
        }
        {
            size_t gidx = (size_t)arow * D_IN + c * 64 + kq;
            uint4 v0 = __ldg(reinterpret_cast<const uint4*>(g_W0T_hi + gidx));
            uint4 v1 = __ldg(reinterpret_cast<const uint4*>(g_W0T_hi + gidx + 8));
            uint4 w0 = __ldg(reinterpret_cast<const uint4*>(g_W0T_lo + gidx));
            uint4 w1 = __ldg(reinterpret_cast<const uint4*>(g_W0T_lo + gidx + 8));
            int off = arow * G1_PAD + kq;
            *reinterpret_cast<uint4*>(BH + off)     = v0;
            *reinterpret_cast<uint4*>(BH + off + 8) = v1;
            *reinterpret_cast<uint4*>(BL + off)     = w0;
            *reinterpret_cast<uint4*>(BL + off + 8) = w1;
        }
        __syncthreads();

        if (c < 7) {
            xsrc += 16;
#pragma unroll
            for (int j = 0; j < 4; j++) xr[j] = __ldg(xsrc + j);
        }

#pragma unroll
        for (int ks = 0; ks < 4; ++ks) {
            uint32_t ah[2][4], al[2][4], bh[4][2], bl[4][2];
#pragma unroll
            for (int t = 0; t < 2; t++) {
                uint32_t aoff = (uint32_t)(((aRow + t * 16) * G1_PAD) +
                                           ks * 16 + aKof) * 2u;
                LDSM4(ah[t][0], ah[t][1], ah[t][2], ah[t][3], ah_base + aoff);
                LDSM4(al[t][0], al[t][1], al[t][2], al[t][3], al_base + aoff);
            }
#pragma unroll
            for (int u = 0; u < 4; u++) {
                uint32_t boff = (uint32_t)(((bRow + u * 8) * G1_PAD) +
                                           ks * 16 + bKof) * 2u;
                LDSM2(bh[u][0], bh[u][1], bh_base + boff);
                LDSM2(bl[u][0], bl[u][1], bl_base + boff);
            }
#pragma unroll
            for (int t = 0; t < 2; t++)
#pragma unroll
                for (int u = 0; u < 4; u++) {
                    MMA16816(acc[t][u], ah[t], bh[u]);
                    MMA16816(acc[t][u], ah[t], bl[u]);
                    MMA16816(acc[t][u], al[t], bh[u]);
                }
        }
        __syncthreads();
    }

    const int erow = lid >> 2;
    const int ecol = (lid & 3) * 2;
#pragma unroll
    for (int t = 0; t < 2; t++) {
#pragma unroll
        for (int u = 0; u < 4; u++) {
            int r0 = mBase + wm * 32 + t * 16 + erow;
            int cc = wn * 32 + u * 8 + ecol;
            if (r0 < N_NODES) {
                __half2 o = __floats2half2_rn(acc[t][u][0], acc[t][u][1]);
                *reinterpret_cast<__half2*>(g_XW0h + (size_t)r0 * D_H + cc) = o;
            }
            int r1 = r0 + 8;
            if (r1 < N_NODES) {
                __half2 o = __floats2half2_rn(acc[t][u][2], acc[t][u][3]);
                *reinterpret_cast<__half2*>(g_XW0h + (size_t)r1 * D_H + cc) = o;
            }
        }
    }
}

// ---------------- SpMM1 fused: H(bf16 hi/lo) = relu(adj@XW0h + b0), BN partials
// 8 nodes per block (grid = 12500 exactly). One warp per node.
// Lane handles channels 4*lane..4*lane+3 -> one 8B gather per edge.
__global__ __launch_bounds__(256) void spmm1_kernel(
        const float* __restrict__ vals, const int* __restrict__ col,
        const float* __restrict__ b0) {
    __shared__ float sh[1024];
    const int tid  = threadIdx.x;
    const int wid  = tid >> 5;
    const int lane = tid & 31;
    const int w = blockIdx.x * 8 + wid;
    const int cb = lane * 4;

    const int s = g_rowptr[w], e = g_rowptr[w + 1];
    float a0 = 0.f, a1 = 0.f, a2 = 0.f, a3 = 0.f;
    int i = s;
    for (; i + 2 <= e; i += 2) {
        float v0 = __ldg(vals + i);
        float v1 = __ldg(vals + i + 1);
        int   c0 = __ldg(col + i);
        int   c1 = __ldg(col + i + 1);
        uint2 q0 = __ldg(reinterpret_cast<const uint2*>(
            g_XW0h + (size_t)c0 * D_H + cb));
        uint2 q1 = __ldg(reinterpret_cast<const uint2*>(
            g_XW0h + (size_t)c1 * D_H + cb));
        float2 f00 = __half22float2(*reinterpret_cast<__half2*>(&q0.x));
        float2 f01 = __half22float2(*reinterpret_cast<__half2*>(&q0.y));
        float2 f10 = __half22float2(*reinterpret_cast<__half2*>(&q1.x));
        float2 f11 = __half22float2(*reinterpret_cast<__half2*>(&q1.y));
        a0 = fmaf(v0, f00.x, a0); a1 = fmaf(v0, f00.y, a1);
        a2 = fmaf(v0, f01.x, a2); a3 = fmaf(v0, f01.y, a3);
        a0 = fmaf(v1, f10.x, a0); a1 = fmaf(v1, f10.y, a1);
        a2 = fmaf(v1, f11.x, a2); a3 = fmaf(v1, f11.y, a3);
    }
    if (i < e) {
        float v = __ldg(vals + i);
        int   c = __ldg(col + i);
        uint2 q = __ldg(reinterpret_cast<const uint2*>(
            g_XW0h + (size_t)c * D_H + cb));
        float2 f0 = __half22float2(*reinterpret_cast<__half2*>(&q.x));
        float2 f1 = __half22float2(*reinterpret_cast<__half2*>(&q.y));
        a0 = fmaf(v, f0.x, a0); a1 = fmaf(v, f0.y, a1);
        a2 = fmaf(v, f1.x, a2); a3 = fmaf(v, f1.y, a3);
    }
    float h0 = fmaxf(a0 + __ldg(b0 + cb),     0.f);
    float h1 = fmaxf(a1 + __ldg(b0 + cb + 1), 0.f);
    float h2 = fmaxf(a2 + __ldg(b0 + cb + 2), 0.f);
    float h3 = fmaxf(a3 + __ldg(b0 + cb + 3), 0.f);

    // write bf16 hi/lo H (channels cb..cb+3 -> one uint2 per stream)
    {
        uint32_t lo01, lo23;
        uint32_t hi01 = bfhi_pack(h0, h1, lo01);
        uint32_t hi23 = bfhi_pack(h2, h3, lo23);
        const size_t base = (size_t)w * D_H + cb;
        *reinterpret_cast<uint2*>(g_Hhi + base) = make_uint2(hi01, hi23);
        *reinterpret_cast<uint2*>(g_Hlo + base) = make_uint2(lo01, lo23);
    }

    // BN partials: block-level (sum, sumsq) per channel, deterministic order
    sh[wid * 128 + cb]     = h0;
    sh[wid * 128 + cb + 1] = h1;
    sh[wid * 128 + cb + 2] = h2;
    sh[wid * 128 + cb + 3] = h3;
    __syncthreads();
    if (tid < 128) {
        float s_ = 0.f, ss_ = 0.f;
#pragma unroll
        for (int j = 0; j < 8; j++) {
            float v = sh[j * 128 + tid];
            s_ += v; ss_ += v * v;
        }
        g_part[blockIdx.x * 256 + tid]       = s_;
        g_part[blockIdx.x * 256 + 128 + tid] = ss_;
    }
}

// ---------------- BN reduce stage 2: 12500 partials -> 100 -----------------
__global__ __launch_bounds__(256) void reduce1_kernel() {
    __shared__ float sh[512];
    int tid = threadIdx.x;
    int ch = tid & 127, half = tid >> 7;
    int b0 = blockIdx.x * 125;
    float s = 0.f, ss = 0.f;
    for (int b = b0 + half; b < b0 + 125; b += 2) {
        s  += g_part[b * 256 + ch];
        ss += g_part[b * 256 + 128 + ch];
    }
    sh[tid] = s; sh[256 + tid] = ss;
    __syncthreads();
    if (half == 0) {
        g_part2[blockIdx.x * 256 + ch]       = s  + sh[tid + 128];
        g_part2[blockIdx.x * 256 + 128 + ch] = ss + sh[256 + tid + 128];
    }
}

// ---------------- BN finalize + fold scale into W1 (bf16 hi/lo, transposed) -
__global__ __launch_bounds__(256) void finalize_kernel(const float* __restrict__ W1) {
    __shared__ float sm[128], sc[128];
    int tid = threadIdx.x;
    if (tid < 128) {
        float s = 0.f, ss = 0.f;
        for (int b = 0; b < RED1_BLOCKS; b++) {
            s  += g_part2[b * 256 + tid];
            ss += g_part2[b * 256 + 128 + tid];
        }
        float mean = s / (float)N_NODES;
        float var = ss / (float)N_NODES - mean * mean;
        if (var < 0.f) var = 0.f;
        sm[tid] = mean;
        sc[tid] = rsqrtf(var + BN_EPS);
    }
    __syncthreads();
    for (int i = tid; i < D_H * D_OUT; i += 256) {
        int k = i >> 6, n = i & 63;
        float w = __ldg(W1 + i) * sc[k];
        __nv_bfloat16 hb = __float2bfloat16(w);
        g_W1T_hi[n * D_H + k] = hb;
        g_W1T_lo[n * D_H + k] = __float2bfloat16(w - __bfloat162float(hb));
    }
    if (tid < 64) {
        float a = 0.f;
        for (int k = 0; k < 128; k++)
            a -= sm[k] * sc[k] * __ldg(W1 + k * 64 + tid);
        g_cvec[tid] = a;
    }
}

// ---------------- GEMM2 via mma.sync: Gh = H @ W1s + cvec (fp16 out) --------
#define G2_PAD 72
#define G2_A_MAT (128 * G2_PAD)
#define G2_B_MAT (64 * G2_PAD)
#define G2_SMEM ((2 * G2_A_MAT + 2 * G2_B_MAT) * 2)   // 55296 bytes

__global__ __launch_bounds__(256, 2) void gemm2_mma_kernel() {
    extern __shared__ __nv_bfloat16 smb2[];
    __nv_bfloat16* AH = smb2;
    __nv_bfloat16* AL = AH + G2_A_MAT;
    __nv_bfloat16* BH = AL + G2_A_MAT;
    __nv_bfloat16* BL = BH + G2_B_MAT;

    const int tid = threadIdx.x;
    const int wid = tid >> 5;
    const int lid = tid & 31;
    const int mBase = blockIdx.x * 128;
    const int wm = wid & 3;
    const int wn = wid >> 2;

    const uint32_t ah_base = smem_u32(AH), al_base = smem_u32(AL);
    const uint32_t bh_base = smem_u32(BH), bl_base = smem_u32(BL);
    const int aRow = wm * 32 + (lid & 7) + 8 * ((lid >> 3) & 1);
    const int aKof = 8 * (lid >> 4);
    const int l2   = lid & 15;
    const int bRow = wn * 32 + (l2 & 7);
    const int bKof = 8 * (l2 >> 3);

    float acc[2][4][4];
#pragma unroll
    for (int t = 0; t < 2; t++)
#pragma unroll
        for (int u = 0; u < 4; u++)
#pragma unroll
            for (int q = 0; q < 4; q++) acc[t][u][q] = 0.f;

    for (int c = 0; c < 2; ++c) {
#pragma unroll
        for (int i = 0; i < 4; ++i) {
            int u = tid + i * 256;
            int r = u >> 3, u8 = u & 7;
            int gr = mBase + r; if (gr >= N_NODES) gr = N_NODES - 1;
            size_t gidx = (size_t)gr * D_H + c * 64 + u8 * 8;
            uint4 vh = __ldg(reinterpret_cast<const uint4*>(g_Hhi + gidx));
            uint4 vl = __ldg(reinterpret_cast<const uint4*>(g_Hlo + gidx));
            *reinterpret_cast<uint4*>(AH + r * G2_PAD + u8 * 8) = vh;
            *reinterpret_cast<uint4*>(AL + r * G2_PAD + u8 * 8) = vl;
        }
#pragma unroll
        for (int i = 0; i < 2; ++i) {
            int u = tid + i * 256;
            int r = u >> 3, u8 = u & 7;
            size_t gidx = (size_t)r * D_H + c * 64 + u8 * 8;
            uint4 vh = __ldg(reinterpret_cast<const uint4*>(g_W1T_hi + gidx));
            uint4 vl = __ldg(reinterpret_cast<const uint4*>(g_W1T_lo + gidx));
            *reinterpret_cast<uint4*>(BH + r * G2_PAD + u8 * 8) = vh;
            *reinterpret_cast<uint4*>(BL + r * G2_PAD + u8 * 8) = vl;
        }
        __syncthreads();

#pragma unroll
        for (int ks = 0; ks < 4; ++ks) {
            uint32_t ah[2][4], al[2][4], bh[4][2], bl[4][2];
#pragma unroll
            for (int t = 0; t < 2; t++) {
                uint32_t aoff = (uint32_t)(((aRow + t * 16) * G2_PAD) +
                                           ks * 16 + aKof) * 2u;
                LDSM4(ah[t][0], ah[t][1], ah[t][2], ah[t][3], ah_base + aoff);
                LDSM4(al[t][0], al[t][1], al[t][2], al[t][3], al_base + aoff);
            }
#pragma unroll
            for (int u = 0; u < 4; u++) {
                uint32_t boff = (uint32_t)(((bRow + u * 8) * G2_PAD) +
                                           ks * 16 + bKof) * 2u;
                LDSM2(bh[u][0], bh[u][1], bh_base + boff);
                LDSM2(bl[u][0], bl[u][1], bl_base + boff);
            }
#pragma unroll
            for (int t = 0; t < 2; t++)
#pragma unroll
                for (int u = 0; u < 4; u++) {
                    MMA16816(acc[t][u], ah[t], bh[u]);
                    MMA16816(acc[t][u], ah[t], bl[u]);
                    MMA16816(acc[t][u], al[t], bh[u]);
                }
        }
        __syncthreads();
    }

    const int erow = lid >> 2;
    const int ecol = (lid & 3) * 2;
#pragma unroll
    for (int t = 0; t < 2; t++) {
#pragma unroll
        for (int u = 0; u < 4; u++) {
            int cc = wn * 32 + u * 8 + ecol;
            float cv0 = g_cvec[cc], cv1 = g_cvec[cc + 1];
            int r0 = mBase + wm * 32 + t * 16 + erow;
            if (r0 < N_NODES) {
                __half2 o = __floats2half2_rn(acc[t][u][0] + cv0,
                                              acc[t][u][1] + cv1);
                *reinterpret_cast<__half2*>(g_Gh + (size_t)r0 * D_OUT + cc) = o;
            }
            int r1 = r0 + 8;
            if (r1 < N_NODES) {
                __half2 o = __floats2half2_rn(acc[t][u][2] + cv0,
                                              acc[t][u][3] + cv1);
                *reinterpret_cast<__half2*>(g_Gh + (size_t)r1 * D_OUT + cc) = o;
            }
        }
    }
}

// ---------------- SpMM2: out = adj @ Gh + b1 (half2 gather) -----------------
// Lane handles channels 2*lane, 2*lane+1 -> one 4B gather per edge.
__global__ __launch_bounds__(256) void spmm2_kernel(
        const float* __restrict__ vals, const int* __restrict__ col,
        const float* __restrict__ b1, float* __restrict__ out) {
    int w = (blockIdx.x * 256 + threadIdx.x) >> 5;
    int lane = threadIdx.x & 31;
    if (w >= N_NODES) return;
    const int cb = lane * 2;
    int s = g_rowptr[w], e = g_rowptr[w + 1];
    float a0 = 0.f, a1 = 0.f;
    int i = s;
    for (; i + 2 <= e; i += 2) {
        float v0 = __ldg(vals + i);
        float v1 = __ldg(vals + i + 1);
        int   c0 = __ldg(col + i);
        int   c1 = __ldg(col + i + 1);
        __half2 q0 = __ldg(reinterpret_cast<const __half2*>(
            g_Gh + (size_t)c0 * D_OUT + cb));
        __half2 q1 = __ldg(reinterpret_cast<const __half2*>(
            g_Gh + (size_t)c1 * D_OUT + cb));
        float2 f0 = __half22float2(q0);
        float2 f1 = __half22float2(q1);
        a0 = fmaf(v0, f0.x, a0); a1 = fmaf(v0, f0.y, a1);
        a0 = fmaf(v1, f1.x, a0); a1 = fmaf(v1, f1.y, a1);
    }
    if (i < e) {
        float v = __ldg(vals + i);
        int   c = __ldg(col + i);
        __half2 q = __ldg(reinterpret_cast<const __half2*>(
            g_Gh + (size_t)c * D_OUT + cb));
        float2 f = __half22float2(q);
        a0 = fmaf(v, f.x, a0); a1 = fmaf(v, f.y, a1);
    }
    float2 o = make_float2(a0 + __ldg(b1 + cb), a1 + __ldg(b1 + cb + 1));
    *reinterpret_cast<float2*>(out + (size_t)w * D_OUT + cb) = o;
}

// ---------------- launch ----------------------------------------------------
extern "C" void kernel_launch(void* const* d_in, const int* in_sizes, int n_in,
                              void* d_out, int out_size) {
    const float* x    = (const float*)d_in[0];
    const float* W0   = (const float*)d_in[1];
    const float* b0   = (const float*)d_in[2];
    const float* W1   = (const float*)d_in[3];
    const float* b1   = (const float*)d_in[4];
    const float* adjv = (const float*)d_in[5];
    const int*   row  = (const int*)d_in[6];
    const int*   col  = (const int*)d_in[7];
    float* out = (float*)d_out;

    cudaFuncSetAttribute(gemm1_mma_kernel,
                         cudaFuncAttributeMaxDynamicSharedMemorySize, G1_SMEM);
    cudaFuncSetAttribute(gemm2_mma_kernel,
                         cudaFuncAttributeMaxDynamicSharedMemorySize, G2_SMEM);

    rowptr_kernel   <<<(N_NODES + 1 + 255) / 256, 256>>>(row);
    prep_w0_kernel  <<<(D_IN * D_H + 255) / 256, 256>>>(W0);
    gemm1_mma_kernel<<<(N_NODES + 127) / 128, 512, G1_SMEM>>>(x);
    spmm1_kernel    <<<SP1_BLOCKS, 256>>>(adjv, col, b0);
    reduce1_kernel  <<<RED1_BLOCKS, 256>>>();
    finalize_kernel <<<1, 256>>>(W1);
    gemm2_mma_kernel<<<(N_NODES + 127) / 128, 256, G2_SMEM>>>();
    spmm2_kernel    <<<(N_NODES + 7) / 8, 256>>>(adjv, col, b1, out);
}

// round 15
// speedup vs baseline: 2.4261x; 1.3654x over previous
#include <cuda_runtime.h>
#include <cuda_bf16.h>
#include <cuda_fp16.h>
#include <cstdint>

#define N_NODES 100000
#define N_EDGES 1600000
#define D_IN    512
#define D_H     128
#define D_OUT   64
#define BN_EPS  1e-5f
#define SP1_BLOCKS (N_NODES / 8)        // 12500, exact
#define RED1_BLOCKS 100                 // 12500 = 100 * 125

// ---------------- scratch (device globals; no allocation allowed) ------------
__device__ __align__(16) __half g_XW0h[(size_t)N_NODES * D_H];  // 25.6 MB
__device__ __align__(16) __half g_Hh  [(size_t)N_NODES * D_H];  // 25.6 MB
__device__ __align__(16) __half g_Gh  [(size_t)N_NODES * D_OUT];// 12.8 MB
__device__ int   g_rowptr[N_NODES + 1];
__device__ float g_part [SP1_BLOCKS * 256];               // 12.8 MB
__device__ float g_part2[RED1_BLOCKS * 256];
__device__ float g_cvec[D_OUT];
__device__ __align__(16) __half g_W0Th[D_H * D_IN];   // [n][k] fp16
__device__ __align__(16) __half g_W1Th[D_OUT * D_H];  // [n][k] fp16, BN-scaled

// ---------------- base-ISA tensor-core helpers (sm_80+, OK on sm_103) --------
__device__ __forceinline__ uint32_t smem_u32(const void* p) {
    uint32_t a;
    asm("{ .reg .u64 t; cvta.to.shared.u64 t, %1; cvt.u32.u64 %0, t; }"
        : "=r"(a) : "l"(p));
    return a;
}
#define LDSM4(r0, r1, r2, r3, addr)                                            \
    asm volatile("ldmatrix.sync.aligned.m8n8.x4.shared.b16 {%0,%1,%2,%3}, [%4];" \
        : "=r"(r0), "=r"(r1), "=r"(r2), "=r"(r3) : "r"(addr))
#define LDSM2(r0, r1, addr)                                                    \
    asm volatile("ldmatrix.sync.aligned.m8n8.x2.shared.b16 {%0,%1}, [%2];"     \
        : "=r"(r0), "=r"(r1) : "r"(addr))
#define MMA16816H(d, a, b)                                                     \
    asm volatile("mma.sync.aligned.m16n8k16.row.col.f32.f16.f16.f32 "          \
        "{%0,%1,%2,%3}, {%4,%5,%6,%7}, {%8,%9}, {%0,%1,%2,%3};"                \
        : "+f"((d)[0]), "+f"((d)[1]), "+f"((d)[2]), "+f"((d)[3])               \
        : "r"((a)[0]), "r"((a)[1]), "r"((a)[2]), "r"((a)[3]),                  \
          "r"((b)[0]), "r"((b)[1]))

// ---------------- CSR offsets from sorted row -------------------------------
__global__ void rowptr_kernel(const int* __restrict__ row) {
    int i = blockIdx.x * blockDim.x + threadIdx.x;
    if (i > N_NODES) return;
    int lo = 0, hi = N_EDGES;
    while (lo < hi) {
        int mid = (lo + hi) >> 1;
        if (__ldg(row + mid) < i) lo = mid + 1; else hi = mid;
    }
    g_rowptr[i] = lo;
}

// ---------------- prep: W0 [512][128] f32 -> W0T fp16 [128][512] ------------
__global__ void prep_w0_kernel(const float* __restrict__ W0) {
    int i = blockIdx.x * 256 + threadIdx.x;
    if (i >= D_IN * D_H) return;
    int k = i >> 7, n = i & 127;
    g_W0Th[n * D_IN + k] = __float2half(__ldg(W0 + i));
}

// ---------------- GEMM1 via mma.sync fp16: XW0 = x @ W0 ---------------------
// CTA tile 128x128, 512 threads = 16 warps (4m x 4n), warp tile 32x32.
// K chunks of 64; single smem buffer, round-11-proven loop structure:
// convert+store -> sync -> reg-prefetch -> MMA -> sync.
#define G1_PAD 72
#define G1_MAT (128 * G1_PAD)
#define G1_SMEM (2 * G1_MAT * 2)        // A + B, 36864 bytes

__global__ __launch_bounds__(512, 1) void gemm1_mma_kernel(
        const float* __restrict__ X) {
    extern __shared__ __half smh[];
    __half* AH = smh;
    __half* BH = smh + G1_MAT;

    const int tid = threadIdx.x;
    const int wid = tid >> 5;
    const int lid = tid & 31;
    const int mBase = blockIdx.x * 128;
    const int wm = wid & 3;
    const int wn = wid >> 2;

    // loader mapping: thread -> (row 0..127, k-quarter of 16 elems)
    const int arow = tid >> 2;
    const int kq   = (tid & 3) * 16;
    int gr = mBase + arow; if (gr >= N_NODES) gr = N_NODES - 1;
    const float4* xsrc = reinterpret_cast<const float4*>(
        X + (size_t)gr * D_IN + kq);
    const uint4* bsrc = reinterpret_cast<const uint4*>(
        g_W0Th + (size_t)arow * D_IN + kq);   // 8 halves per uint4

    const uint32_t ah_base = smem_u32(AH);
    const uint32_t bh_base = smem_u32(BH);
    const int aRow = wm * 32 + (lid & 7) + 8 * ((lid >> 3) & 1);
    const int aKof = 8 * (lid >> 4);
    const int l2   = lid & 15;
    const int bRow = wn * 32 + (l2 & 7);
    const int bKof = 8 * (l2 >> 3);

    float acc[2][4][4];
#pragma unroll
    for (int t = 0; t < 2; t++)
#pragma unroll
        for (int u = 0; u < 4; u++)
#pragma unroll
            for (int q = 0; q < 4; q++) acc[t][u][q] = 0.f;

    float4 xr[4];
    uint4  br[2];
#pragma unroll
    for (int j = 0; j < 4; j++) xr[j] = __ldg(xsrc + j);
    br[0] = __ldg(bsrc);
    br[1] = __ldg(bsrc + 1);

    for (int c = 0; c < 8; ++c) {
        // --- convert A chunk regs -> smem fp16; copy B chunk ----------------
        {
            uint32_t h[8];
#pragma unroll
            for (int j = 0; j < 4; j++) {
                __half2 p0 = __floats2half2_rn(xr[j].x, xr[j].y);
                __half2 p1 = __floats2half2_rn(xr[j].z, xr[j].w);
                h[2 * j]     = *reinterpret_cast<uint32_t*>(&p0);
                h[2 * j + 1] = *reinterpret_cast<uint32_t*>(&p1);
            }
            int off = arow * G1_PAD + kq;
            *reinterpret_cast<uint4*>(AH + off)     = make_uint4(h[0], h[1], h[2], h[3]);
            *reinterpret_cast<uint4*>(AH + off + 8) = make_uint4(h[4], h[5], h[6], h[7]);
            *reinterpret_cast<uint4*>(BH + off)     = br[0];
            *reinterpret_cast<uint4*>(BH + off + 8) = br[1];
        }
        __syncthreads();

        // --- prefetch next chunk to regs (overlaps MMA below) ---------------
        if (c < 7) {
            xsrc += 16;  bsrc += 8;
#pragma unroll
            for (int j = 0; j < 4; j++) xr[j] = __ldg(xsrc + j);
            br[0] = __ldg(bsrc);
            br[1] = __ldg(bsrc + 1);
        }

        // --- MMA over 4 ksteps of 16 (single fp16 term) ---------------------
#pragma unroll
        for (int ks = 0; ks < 4; ++ks) {
            uint32_t ah[2][4], bh[4][2];
#pragma unroll
            for (int t = 0; t < 2; t++) {
                uint32_t aoff = (uint32_t)(((aRow + t * 16) * G1_PAD) +
                                           ks * 16 + aKof) * 2u;
                LDSM4(ah[t][0], ah[t][1], ah[t][2], ah[t][3], ah_base + aoff);
            }
#pragma unroll
            for (int u = 0; u < 4; u++) {
                uint32_t boff = (uint32_t)(((bRow + u * 8) * G1_PAD) +
                                           ks * 16 + bKof) * 2u;
                LDSM2(bh[u][0], bh[u][1], bh_base + boff);
            }
#pragma unroll
            for (int t = 0; t < 2; t++)
#pragma unroll
                for (int u = 0; u < 4; u++)
                    MMA16816H(acc[t][u], ah[t], bh[u]);
        }
        __syncthreads();
    }

    const int erow = lid >> 2;
    const int ecol = (lid & 3) * 2;
#pragma unroll
    for (int t = 0; t < 2; t++) {
#pragma unroll
        for (int u = 0; u < 4; u++) {
            int r0 = mBase + wm * 32 + t * 16 + erow;
            int cc = wn * 32 + u * 8 + ecol;
            if (r0 < N_NODES) {
                __half2 o = __floats2half2_rn(acc[t][u][0], acc[t][u][1]);
                *reinterpret_cast<__half2*>(g_XW0h + (size_t)r0 * D_H + cc) = o;
            }
            int r1 = r0 + 8;
            if (r1 < N_NODES) {
                __half2 o = __floats2half2_rn(acc[t][u][2], acc[t][u][3]);
                *reinterpret_cast<__half2*>(g_XW0h + (size_t)r1 * D_H + cc) = o;
            }
        }
    }
}

// ---------------- SpMM1 fused: Hh(fp16) = relu(adj@XW0h + b0), BN partials --
// 8 nodes per block (grid = 12500 exactly). One warp per node.
// Lane handles channels 4*lane..4*lane+3 -> one 8B gather per edge.
__global__ __launch_bounds__(256) void spmm1_kernel(
        const float* __restrict__ vals, const int* __restrict__ col,
        const float* __restrict__ b0) {
    __shared__ float sh[1024];
    const int tid  = threadIdx.x;
    const int wid  = tid >> 5;
    const int lane = tid & 31;
    const int w = blockIdx.x * 8 + wid;
    const int cb = lane * 4;

    const int s = g_rowptr[w], e = g_rowptr[w + 1];
    float a0 = 0.f, a1 = 0.f, a2 = 0.f, a3 = 0.f;
    int i = s;
    for (; i + 2 <= e; i += 2) {
        float v0 = __ldg(vals + i);
        float v1 = __ldg(vals + i + 1);
        int   c0 = __ldg(col + i);
        int   c1 = __ldg(col + i + 1);
        uint2 q0 = __ldg(reinterpret_cast<const uint2*>(
            g_XW0h + (size_t)c0 * D_H + cb));
        uint2 q1 = __ldg(reinterpret_cast<const uint2*>(
            g_XW0h + (size_t)c1 * D_H + cb));
        float2 f00 = __half22float2(*reinterpret_cast<__half2*>(&q0.x));
        float2 f01 = __half22float2(*reinterpret_cast<__half2*>(&q0.y));
        float2 f10 = __half22float2(*reinterpret_cast<__half2*>(&q1.x));
        float2 f11 = __half22float2(*reinterpret_cast<__half2*>(&q1.y));
        a0 = fmaf(v0, f00.x, a0); a1 = fmaf(v0, f00.y, a1);
        a2 = fmaf(v0, f01.x, a2); a3 = fmaf(v0, f01.y, a3);
        a0 = fmaf(v1, f10.x, a0); a1 = fmaf(v1, f10.y, a1);
        a2 = fmaf(v1, f11.x, a2); a3 = fmaf(v1, f11.y, a3);
    }
    if (i < e) {
        float v = __ldg(vals + i);
        int   c = __ldg(col + i);
        uint2 q = __ldg(reinterpret_cast<const uint2*>(
            g_XW0h + (size_t)c * D_H + cb));
        float2 f0 = __half22float2(*reinterpret_cast<__half2*>(&q.x));
        float2 f1 = __half22float2(*reinterpret_cast<__half2*>(&q.y));
        a0 = fmaf(v, f0.x, a0); a1 = fmaf(v, f0.y, a1);
        a2 = fmaf(v, f1.x, a2); a3 = fmaf(v, f1.y, a3);
    }
    float h0 = fmaxf(a0 + __ldg(b0 + cb),     0.f);
    float h1 = fmaxf(a1 + __ldg(b0 + cb + 1), 0.f);
    float h2 = fmaxf(a2 + __ldg(b0 + cb + 2), 0.f);
    float h3 = fmaxf(a3 + __ldg(b0 + cb + 3), 0.f);

    // write fp16 H (channels cb..cb+3 -> one 8B store)
    {
        __half2 p01 = __floats2half2_rn(h0, h1);
        __half2 p23 = __floats2half2_rn(h2, h3);
        uint2 o = make_uint2(*reinterpret_cast<uint32_t*>(&p01),
                             *reinterpret_cast<uint32_t*>(&p23));
        *reinterpret_cast<uint2*>(g_Hh + (size_t)w * D_H + cb) = o;
    }

    // BN partials: block-level (sum, sumsq) per channel, deterministic order
    sh[wid * 128 + cb]     = h0;
    sh[wid * 128 + cb + 1] = h1;
    sh[wid * 128 + cb + 2] = h2;
    sh[wid * 128 + cb + 3] = h3;
    __syncthreads();
    if (tid < 128) {
        float s_ = 0.f, ss_ = 0.f;
#pragma unroll
        for (int j = 0; j < 8; j++) {
            float v = sh[j * 128 + tid];
            s_ += v; ss_ += v * v;
        }
        g_part[blockIdx.x * 256 + tid]       = s_;
        g_part[blockIdx.x * 256 + 128 + tid] = ss_;
    }
}

// ---------------- BN reduce stage 2: 12500 partials -> 100 -----------------
__global__ __launch_bounds__(256) void reduce1_kernel() {
    __shared__ float sh[512];
    int tid = threadIdx.x;
    int ch = tid & 127, half = tid >> 7;
    int b0 = blockIdx.x * 125;
    float s = 0.f, ss = 0.f;
    for (int b = b0 + half; b < b0 + 125; b += 2) {
        s  += g_part[b * 256 + ch];
        ss += g_part[b * 256 + 128 + ch];
    }
    sh[tid] = s; sh[256 + tid] = ss;
    __syncthreads();
    if (half == 0) {
        g_part2[blockIdx.x * 256 + ch]       = s  + sh[tid + 128];
        g_part2[blockIdx.x * 256 + 128 + ch] = ss + sh[256 + tid + 128];
    }
}

// ---------------- BN finalize + fold scale into W1 (fp16, transposed) -------
__global__ __launch_bounds__(256) void finalize_kernel(const float* __restrict__ W1) {
    __shared__ float sm[128], sc[128];
    int tid = threadIdx.x;
    if (tid < 128) {
        float s = 0.f, ss = 0.f;
        for (int b = 0; b < RED1_BLOCKS; b++) {
            s  += g_part2[b * 256 + tid];
            ss += g_part2[b * 256 + 128 + tid];
        }
        float mean = s / (float)N_NODES;
        float var = ss / (float)N_NODES - mean * mean;
        if (var < 0.f) var = 0.f;
        sm[tid] = mean;
        sc[tid] = rsqrtf(var + BN_EPS);
    }
    __syncthreads();
    for (int i = tid; i < D_H * D_OUT; i += 256) {
        int k = i >> 6, n = i & 63;
        g_W1Th[n * D_H + k] = __float2half(__ldg(W1 + i) * sc[k]);
    }
    if (tid < 64) {
        float a = 0.f;
        for (int k = 0; k < 128; k++)
            a -= sm[k] * sc[k] * __ldg(W1 + k * 64 + tid);
        g_cvec[tid] = a;
    }
}

// ---------------- GEMM2 via mma.sync fp16: Gh = Hh @ W1Th + cvec ------------
// CTA 128(M) x 64(N), 256 threads = 8 warps (4m x 2n), warp tile 32x32.
#define G2_PAD 72
#define G2_A_MAT (128 * G2_PAD)
#define G2_B_MAT (64 * G2_PAD)
#define G2_SMEM ((G2_A_MAT + G2_B_MAT) * 2)   // 27648 bytes

__global__ __launch_bounds__(256, 2) void gemm2_mma_kernel() {
    extern __shared__ __half smh2[];
    __half* AH = smh2;
    __half* BH = AH + G2_A_MAT;

    const int tid = threadIdx.x;
    const int wid = tid >> 5;
    const int lid = tid & 31;
    const int mBase = blockIdx.x * 128;
    const int wm = wid & 3;
    const int wn = wid >> 2;

    const uint32_t ah_base = smem_u32(AH);
    const uint32_t bh_base = smem_u32(BH);
    const int aRow = wm * 32 + (lid & 7) + 8 * ((lid >> 3) & 1);
    const int aKof = 8 * (lid >> 4);
    const int l2   = lid & 15;
    const int bRow = wn * 32 + (l2 & 7);
    const int bKof = 8 * (l2 >> 3);

    float acc[2][4][4];
#pragma unroll
    for (int t = 0; t < 2; t++)
#pragma unroll
        for (int u = 0; u < 4; u++)
#pragma unroll
            for (int q = 0; q < 4; q++) acc[t][u][q] = 0.f;

    for (int c = 0; c < 2; ++c) {
        // A copy: 128 rows x 64 fp16
#pragma unroll
        for (int i = 0; i < 4; ++i) {
            int u = tid + i * 256;
            int r = u >> 3, u8 = u & 7;
            int gr = mBase + r; if (gr >= N_NODES) gr = N_NODES - 1;
            size_t gidx = (size_t)gr * D_H + c * 64 + u8 * 8;
            *reinterpret_cast<uint4*>(AH + r * G2_PAD + u8 * 8) =
                __ldg(reinterpret_cast<const uint4*>(g_Hh + gidx));
        }
        // B copy: 64 rows x 64 fp16
#pragma unroll
        for (int i = 0; i < 2; ++i) {
            int u = tid + i * 256;
            int r = u >> 3, u8 = u & 7;
            size_t gidx = (size_t)r * D_H + c * 64 + u8 * 8;
            *reinterpret_cast<uint4*>(BH + r * G2_PAD + u8 * 8) =
                __ldg(reinterpret_cast<const uint4*>(g_W1Th + gidx));
        }
        __syncthreads();

#pragma unroll
        for (int ks = 0; ks < 4; ++ks) {
            uint32_t ah[2][4], bh[4][2];
#pragma unroll
            for (int t = 0; t < 2; t++) {
                uint32_t aoff = (uint32_t)(((aRow + t * 16) * G2_PAD) +
                                           ks * 16 + aKof) * 2u;
                LDSM4(ah[t][0], ah[t][1], ah[t][2], ah[t][3], ah_base + aoff);
            }
#pragma unroll
            for (int u = 0; u < 4; u++) {
                uint32_t boff = (uint32_t)(((bRow + u * 8) * G2_PAD) +
                                           ks * 16 + bKof) * 2u;
                LDSM2(bh[u][0], bh[u][1], bh_base + boff);
            }
#pragma unroll
            for (int t = 0; t < 2; t++)
#pragma unroll
                for (int u = 0; u < 4; u++)
                    MMA16816H(acc[t][u], ah[t], bh[u]);
        }
        __syncthreads();
    }

    const int erow = lid >> 2;
    const int ecol = (lid & 3) * 2;
#pragma unroll
    for (int t = 0; t < 2; t++) {
#pragma unroll
        for (int u = 0; u < 4; u++) {
            int cc = wn * 32 + u * 8 + ecol;
            float cv0 = g_cvec[cc], cv1 = g_cvec[cc + 1];
            int r0 = mBase + wm * 32 + t * 16 + erow;
            if (r0 < N_NODES) {
                __half2 o = __floats2half2_rn(acc[t][u][0] + cv0,
                                              acc[t][u][1] + cv1);
                *reinterpret_cast<__half2*>(g_Gh + (size_t)r0 * D_OUT + cc) = o;
            }
            int r1 = r0 + 8;
            if (r1 < N_NODES) {
                __half2 o = __floats2half2_rn(acc[t][u][2] + cv0,
                                              acc[t][u][3] + cv1);
                *reinterpret_cast<__half2*>(g_Gh + (size_t)r1 * D_OUT + cc) = o;
            }
        }
    }
}

// ---------------- SpMM2: out = adj @ Gh + b1 (half2 gather) -----------------
__global__ __launch_bounds__(256) void spmm2_kernel(
        const float* __restrict__ vals, const int* __restrict__ col,
        const float* __restrict__ b1, float* __restrict__ out) {
    int w = (blockIdx.x * 256 + threadIdx.x) >> 5;
    int lane = threadIdx.x & 31;
    if (w >= N_NODES) return;
    const int cb = lane * 2;
    int s = g_rowptr[w], e = g_rowptr[w + 1];
    float a0 = 0.f, a1 = 0.f;
    int i = s;
    for (; i + 2 <= e; i += 2) {
        float v0 = __ldg(vals + i);
        float v1 = __ldg(vals + i + 1);
        int   c0 = __ldg(col + i);
        int   c1 = __ldg(col + i + 1);
        __half2 q0 = __ldg(reinterpret_cast<const __half2*>(
            g_Gh + (size_t)c0 * D_OUT + cb));
        __half2 q1 = __ldg(reinterpret_cast<const __half2*>(
            g_Gh + (size_t)c1 * D_OUT + cb));
        float2 f0 = __half22float2(q0);
        float2 f1 = __half22float2(q1);
        a0 = fmaf(v0, f0.x, a0); a1 = fmaf(v0, f0.y, a1);
        a0 = fmaf(v1, f1.x, a0); a1 = fmaf(v1, f1.y, a1);
    }
    if (i < e) {
        float v = __ldg(vals + i);
        int   c = __ldg(col + i);
        __half2 q = __ldg(reinterpret_cast<const __half2*>(
            g_Gh + (size_t)c * D_OUT + cb));
        float2 f = __half22float2(q);
        a0 = fmaf(v, f.x, a0); a1 = fmaf(v, f.y, a1);
    }
    float2 o = make_float2(a0 + __ldg(b1 + cb), a1 + __ldg(b1 + cb + 1));
    *reinterpret_cast<float2*>(out + (size_t)w * D_OUT + cb) = o;
}

// ---------------- launch ----------------------------------------------------
extern "C" void kernel_launch(void* const* d_in, const int* in_sizes, int n_in,
                              void* d_out, int out_size) {
    const float* x    = (const float*)d_in[0];
    const float* W0   = (const float*)d_in[1];
    const float* b0   = (const float*)d_in[2];
    const float* W1   = (const float*)d_in[3];
    const float* b1   = (const float*)d_in[4];
    const float* adjv = (const float*)d_in[5];
    const int*   row  = (const int*)d_in[6];
    const int*   col  = (const int*)d_in[7];
    float* out = (float*)d_out;

    cudaFuncSetAttribute(gemm1_mma_kernel,
                         cudaFuncAttributeMaxDynamicSharedMemorySize, G1_SMEM);
    cudaFuncSetAttribute(gemm2_mma_kernel,
                         cudaFuncAttributeMaxDynamicSharedMemorySize, G2_SMEM);

    rowptr_kernel   <<<(N_NODES + 1 + 255) / 256, 256>>>(row);
    prep_w0_kernel  <<<(D_IN * D_H + 255) / 256, 256>>>(W0);
    gemm1_mma_kernel<<<(N_NODES + 127) / 128, 512, G1_SMEM>>>(x);
    spmm1_kernel    <<<SP1_BLOCKS, 256>>>(adjv, col, b0);
    reduce1_kernel  <<<RED1_BLOCKS, 256>>>();
    finalize_kernel <<<1, 256>>>(W1);
    gemm2_mma_kernel<<<(N_NODES + 127) / 128, 256, G2_SMEM>>>();
    spmm2_kernel    <<<(N_NODES + 7) / 8, 256>>>(adjv, col, b1, out);
}